// round 2
// baseline (speedup 1.0000x reference)
#include <cuda_runtime.h>

#define NNODES 50000
#define NEDGES 800000
#define FIN0   128      // NFEAT
#define F1     204      // 64 + 68 + 72
#define F2     260      // 132 + 128

// ---------------- device scratch (static, allowed) ----------------
__device__ float g_H[(size_t)NNODES * F2];     // GEMM1 out (stride 204) then GEMM2 out (stride 260)
__device__ float g_fou[(size_t)NNODES * 132];  // h_fou
__device__ float g_Wc1[FIN0 * F1];
__device__ float g_bc1[F1];
__device__ float g_Wc2[F1 * F2];
__device__ float g_bc2[F2];
__device__ int   g_rowptr[NNODES + 1];
__device__ int   g_cnt[NNODES];
__device__ int   g_ecol[NEDGES];
__device__ float g_eval[NEDGES];

// ---------------- weight packing ----------------
__global__ void pack_kernel(const float* __restrict__ W1, const float* __restrict__ b1,
                            const float* __restrict__ W2, const float* __restrict__ b2,
                            const float* __restrict__ W3, const float* __restrict__ b3,
                            const float* __restrict__ W4, const float* __restrict__ b4,
                            const float* __restrict__ W5, const float* __restrict__ b5) {
    int i = blockIdx.x * blockDim.x + threadIdx.x;
    if (i < FIN0 * F1) {
        int k = i / F1, c = i % F1;
        float v = (c < 64) ? W1[k * 64 + c]
                : (c < 132) ? W2[k * 68 + (c - 64)]
                            : W3[k * 72 + (c - 132)];
        g_Wc1[i] = v;
    }
    int j = i - FIN0 * F1;
    if (j >= 0 && j < F1 * F2) {
        int k = j / F2, c = j % F2;
        g_Wc2[j] = (c < 132) ? W4[k * 132 + c] : W5[k * 128 + (c - 132)];
    }
    if (i < F1) g_bc1[i] = (i < 64) ? b1[i] : (i < 132) ? b2[i - 64] : b3[i - 132];
    if (i < F2) g_bc2[i] = (i < 132) ? b4[i] : b5[i - 132];
}

// ---------------- CSR build (indices are INT32: row = idx[e], col = idx[E+e]) ----------------
__global__ void zero_cnt_kernel() {
    int i = blockIdx.x * blockDim.x + threadIdx.x;
    if (i < NNODES) g_cnt[i] = 0;
}

__global__ void hist_kernel(const int* __restrict__ idx) {
    int stride = gridDim.x * blockDim.x;
    for (int e = blockIdx.x * blockDim.x + threadIdx.x; e < NEDGES; e += stride)
        atomicAdd(&g_cnt[idx[e]], 1);
}

__global__ void scan_kernel() {
    __shared__ int ssum[1024];
    const int t = threadIdx.x;
    const int chunk = (NNODES + 1023) / 1024;   // 49
    const int base = t * chunk;
    int s = 0;
    for (int j = 0; j < chunk; j++) {
        int idx = base + j;
        if (idx < NNODES) s += g_cnt[idx];
    }
    ssum[t] = s;
    __syncthreads();
    for (int off = 1; off < 1024; off <<= 1) {
        int v = (t >= off) ? ssum[t - off] : 0;
        __syncthreads();
        ssum[t] += v;
        __syncthreads();
    }
    int run = ssum[t] - s;   // exclusive prefix
    for (int j = 0; j < chunk; j++) {
        int idx = base + j;
        if (idx < NNODES) { g_rowptr[idx] = run; run += g_cnt[idx]; }
    }
    if (t == 1023) g_rowptr[NNODES] = ssum[1023];
}

__global__ void fill_kernel(const int* __restrict__ idx, const float* __restrict__ val) {
    int stride = gridDim.x * blockDim.x;
    for (int e = blockIdx.x * blockDim.x + threadIdx.x; e < NEDGES; e += stride) {
        int r = idx[e];
        int pos = g_rowptr[r] + atomicAdd(&g_cnt[r], 1);
        g_ecol[pos] = idx[NEDGES + e];
        g_eval[pos] = val[e];
    }
}

// ---------------- tiled fp32 GEMM: C = act(A @ B + bias) ----------------
// A: [M,K] row-major, B: [K,Nc] row-major, C: [M,Nc]
#define BM 128
#define BN 64
#define BK 16
#define TM 8
#define TN 4
__global__ void __launch_bounds__(256) gemm_kernel(
    const float* __restrict__ A, const float* __restrict__ B, float* __restrict__ C,
    int M, int K, int Nc, const float* __restrict__ bias, int act) {
    __shared__ float As[BK][BM + 4];
    __shared__ float Bs[BK][BN];
    const int tid = threadIdx.x;
    const int row0 = blockIdx.y * BM;
    const int col0 = blockIdx.x * BN;
    const int tx = tid & 15, ty = tid >> 4;
    const int rbase = ty * TM;
    const int cbase = tx * TN;
    float acc[TM][TN];
#pragma unroll
    for (int i = 0; i < TM; i++)
#pragma unroll
        for (int j = 0; j < TN; j++) acc[i][j] = 0.f;

    for (int k0 = 0; k0 < K; k0 += BK) {
#pragma unroll
        for (int l = 0; l < (BM * BK) / 256; l++) {
            int idx = tid + l * 256;
            int r = idx >> 4, kk = idx & 15;
            int gr = row0 + r, gk = k0 + kk;
            As[kk][r] = (gr < M && gk < K) ? A[(size_t)gr * K + gk] : 0.f;
        }
#pragma unroll
        for (int l = 0; l < (BN * BK) / 256; l++) {
            int idx = tid + l * 256;
            int c = idx & 63, kk = idx >> 6;
            int gk = k0 + kk, gc = col0 + c;
            Bs[kk][c] = (gk < K && gc < Nc) ? B[(size_t)gk * Nc + gc] : 0.f;
        }
        __syncthreads();
#pragma unroll
        for (int k = 0; k < BK; k++) {
            float a[TM], b[TN];
#pragma unroll
            for (int i = 0; i < TM; i++) a[i] = As[k][rbase + i];
#pragma unroll
            for (int j = 0; j < TN; j++) b[j] = Bs[k][cbase + j];
#pragma unroll
            for (int i = 0; i < TM; i++)
#pragma unroll
                for (int j = 0; j < TN; j++) acc[i][j] += a[i] * b[j];
        }
        __syncthreads();
    }
#pragma unroll
    for (int i = 0; i < TM; i++) {
        int gr = row0 + rbase + i;
        if (gr >= M) continue;
#pragma unroll
        for (int j = 0; j < TN; j++) {
            int gc = col0 + cbase + j;
            if (gc >= Nc) continue;
            float v = acc[i][j];
            if (bias) v += bias[gc];
            if (act == 1) v = (v > 0.f) ? v : 0.01f * v;   // leaky_relu 0.01
            C[(size_t)gr * Nc + gc] = v;
        }
    }
}

// ---------------- SpMM1 fused: spmm + bias + sigmoid + mean(h_sec)*h_thi concat ----------------
__global__ void __launch_bounds__(224) spmm1_kernel(float* __restrict__ low_out) {
    const int i = blockIdx.x, t = threadIdx.x;
    const int s0 = g_rowptr[i], s1 = g_rowptr[i + 1];
    __shared__ int   sc[64];
    __shared__ float sv[64];
    float acc = 0.f;
    for (int base = s0; base < s1; base += 64) {
        int n = min(64, s1 - base);
        for (int l = t; l < n; l += 224) { sc[l] = g_ecol[base + l]; sv[l] = g_eval[base + l]; }
        __syncthreads();
        if (t < F1) {
            for (int e = 0; e < n; e++)
                acc += sv[e] * g_H[(size_t)sc[e] * F1 + t];
        }
        __syncthreads();
    }
    float v = 0.f;
    if (t < F1) {
        float z = acc + g_bc1[t];
        v = 1.f / (1.f + __expf(-z));
    }
    __shared__ float red[256];
    red[t] = (t >= 64 && t < 132) ? v : 0.f;   // h_sec block
    if (t < 32) red[224 + t] = 0.f;
    __syncthreads();
    for (int s = 128; s > 0; s >>= 1) {
        if (t < s) red[t] += red[t + s];
        __syncthreads();
    }
    float mean = red[0] * (1.f / 68.f);
    if (t < F1) {
        float lr = (t < 132) ? v : mean * v;   // [h_fir, h_sec, mean(h_sec)*h_thi]
        low_out[(size_t)i * F1 + t] = lr;
    }
}

// ---------------- SpMM2: spmm + bias -> h_fou (scratch), h_fiv (out) ----------------
__global__ void __launch_bounds__(288) spmm2_kernel(float* __restrict__ fiv_out) {
    const int i = blockIdx.x, t = threadIdx.x;
    const int s0 = g_rowptr[i], s1 = g_rowptr[i + 1];
    __shared__ int   sc[64];
    __shared__ float sv[64];
    float acc = 0.f;
    for (int base = s0; base < s1; base += 64) {
        int n = min(64, s1 - base);
        for (int l = t; l < n; l += 288) { sc[l] = g_ecol[base + l]; sv[l] = g_eval[base + l]; }
        __syncthreads();
        if (t < F2) {
            for (int e = 0; e < n; e++)
                acc += sv[e] * g_H[(size_t)sc[e] * F2 + t];
        }
        __syncthreads();
    }
    if (t < F2) {
        float z = acc + g_bc2[t];
        if (t < 132) g_fou[(size_t)i * 132 + t] = z;
        else         fiv_out[(size_t)i * 128 + (t - 132)] = z;
    }
}

// ---------------- final: low = mean(lr)*lr + lr ; f3 = (mlp + fou)/2 ----------------
__global__ void __launch_bounds__(384) final_kernel(const float* __restrict__ low,
                                                    const float* __restrict__ mlp,
                                                    float* __restrict__ fin) {
    const int i = blockIdx.x, t = threadIdx.x;
    float lr = (t < 204) ? low[(size_t)i * 204 + t] : 0.f;
    __shared__ float red[512];
    red[t] = (t < 204) ? lr : 0.f;
    if (t < 128) red[384 + t] = 0.f;
    __syncthreads();
    for (int s = 256; s > 0; s >>= 1) {
        if (t < s) red[t] += red[t + s];
        __syncthreads();
    }
    float mean = red[0] * (1.f / 204.f);
    if (t < 204) {
        fin[(size_t)i * 336 + t] = mean * lr + lr;
    } else if (t < 336) {
        int j = t - 204;
        fin[(size_t)i * 336 + t] = 0.5f * (mlp[(size_t)i * 132 + j] + g_fou[(size_t)i * 132 + j]);
    }
}

// ---------------- launch ----------------
extern "C" void kernel_launch(void* const* d_in, const int* in_sizes, int n_in,
                              void* d_out, int out_size) {
    const float* x  = (const float*)d_in[0];
    const int*   a1 = (const int*)d_in[1];
    const float* v1 = (const float*)d_in[2];
    const float* y  = (const float*)d_in[3];
    const int*   a2 = (const int*)d_in[4];
    const float* v2 = (const float*)d_in[5];
    const float* W1 = (const float*)d_in[6];
    const float* b1 = (const float*)d_in[7];
    const float* W2 = (const float*)d_in[8];
    const float* b2 = (const float*)d_in[9];
    const float* W3 = (const float*)d_in[10];
    const float* b3 = (const float*)d_in[11];
    const float* W4 = (const float*)d_in[12];
    const float* b4 = (const float*)d_in[13];
    const float* W5 = (const float*)d_in[14];
    const float* b5 = (const float*)d_in[15];
    const float* Wm = (const float*)d_in[16];
    const float* bm = (const float*)d_in[17];
    float* out = (float*)d_out;

    void* p;
    float *dH, *dWc1, *dWc2;
    cudaGetSymbolAddress(&p, g_H);   dH   = (float*)p;
    cudaGetSymbolAddress(&p, g_Wc1); dWc1 = (float*)p;
    cudaGetSymbolAddress(&p, g_Wc2); dWc2 = (float*)p;

    const size_t N = NNODES;
    const size_t O_XLOW = 0;
    const size_t O_YLOW = N * 204;
    const size_t O_XFIN = 2 * N * 204;
    const size_t O_YFIN = 2 * N * 204 + N * 336;
    const size_t O_XFIV = 2 * N * 204 + 2 * N * 336;
    const size_t O_XMLP = O_XFIV + N * 128;
    const size_t O_YFIV = O_XMLP + N * 132;
    const size_t O_YMLP = O_YFIV + N * 128;

    pack_kernel<<<(FIN0 * F1 + F1 * F2 + 255) / 256, 256>>>(W1, b1, W2, b2, W3, b3, W4, b4, W5, b5);

    const int MROWBLKS = (NNODES + BM - 1) / BM;   // 391

    for (int b = 0; b < 2; b++) {
        const float* X   = b ? y  : x;
        const int*   adj = b ? a2 : a1;
        const float* ev  = b ? v2 : v1;
        float* lowo = out + (b ? O_YLOW : O_XLOW);
        float* fino = out + (b ? O_YFIN : O_XFIN);
        float* fivo = out + (b ? O_YFIV : O_XFIV);
        float* mlpo = out + (b ? O_YMLP : O_XMLP);

        // CSR build
        zero_cnt_kernel<<<(NNODES + 255) / 256, 256>>>();
        hist_kernel<<<1024, 256>>>(adj);
        scan_kernel<<<1, 1024>>>();
        zero_cnt_kernel<<<(NNODES + 255) / 256, 256>>>();
        fill_kernel<<<1024, 256>>>(adj, ev);

        // H1 = X @ [W1|W2|W3]
        gemm_kernel<<<dim3(4, MROWBLKS), 256>>>(X, dWc1, dH, NNODES, 128, 204, nullptr, 0);
        // low_result = fused spmm+sigmoid+concat
        spmm1_kernel<<<NNODES, 224>>>(lowo);
        // G2 = low_result @ [W4|W5]
        gemm_kernel<<<dim3(5, MROWBLKS), 256>>>(lowo, dWc2, dH, NNODES, 204, 260, nullptr, 0);
        // spmm -> h_fou (scratch) + h_fiv (output)
        spmm2_kernel<<<NNODES, 288>>>(fivo);
        // h_mlp = leaky_relu(h_fiv @ Wm + bm)
        gemm_kernel<<<dim3(3, MROWBLKS), 256>>>(fivo, Wm, mlpo, NNODES, 128, 132, bm, 1);
        // final
        final_kernel<<<NNODES, 384>>>(lowo, mlpo, fino);
    }
}

// round 3
// speedup vs baseline: 1.0957x; 1.0957x over previous
#include <cuda_runtime.h>

#define NNODES 50000
#define NEDGES 800000
#define FIN0   128      // NFEAT
#define F1     204      // 64 + 68 + 72
#define F2     260      // 132 + 128

// ---------------- device scratch (static, allowed) ----------------
__device__ float g_H[(size_t)NNODES * F2];     // GEMM1 out (stride 204) then GEMM2 out (stride 260)
__device__ float g_fou[(size_t)NNODES * 132];  // h_fou
__device__ float g_Wc1[FIN0 * F1];
__device__ float g_bc1[F1];
__device__ float g_Wc2[F1 * F2];
__device__ float g_bc2[F2];
__device__ int   g_rowptr[NNODES + 1];
__device__ int   g_cnt[NNODES];
__device__ int   g_ecol[NEDGES];
__device__ float g_eval[NEDGES];

#define SCAN_BLK 1024
#define SCAN_NB  ((NNODES + SCAN_BLK - 1) / SCAN_BLK)   // 49
__device__ int g_bsum[SCAN_NB];
__device__ int g_boff[SCAN_NB];

// ---------------- weight packing ----------------
__global__ void pack_kernel(const float* __restrict__ W1, const float* __restrict__ b1,
                            const float* __restrict__ W2, const float* __restrict__ b2,
                            const float* __restrict__ W3, const float* __restrict__ b3,
                            const float* __restrict__ W4, const float* __restrict__ b4,
                            const float* __restrict__ W5, const float* __restrict__ b5) {
    int i = blockIdx.x * blockDim.x + threadIdx.x;
    if (i < FIN0 * F1) {
        int k = i / F1, c = i % F1;
        float v = (c < 64) ? W1[k * 64 + c]
                : (c < 132) ? W2[k * 68 + (c - 64)]
                            : W3[k * 72 + (c - 132)];
        g_Wc1[i] = v;
    }
    int j = i - FIN0 * F1;
    if (j >= 0 && j < F1 * F2) {
        int k = j / F2, c = j % F2;
        g_Wc2[j] = (c < 132) ? W4[k * 132 + c] : W5[k * 128 + (c - 132)];
    }
    if (i < F1) g_bc1[i] = (i < 64) ? b1[i] : (i < 132) ? b2[i - 64] : b3[i - 132];
    if (i < F2) g_bc2[i] = (i < 132) ? b4[i] : b5[i - 132];
}

// ---------------- CSR build (indices INT32: row = idx[e], col = idx[E+e]) ----------------
__global__ void zero_cnt_kernel() {
    int i = blockIdx.x * blockDim.x + threadIdx.x;
    if (i < NNODES) g_cnt[i] = 0;
}

__global__ void hist_kernel(const int* __restrict__ idx) {
    int stride = gridDim.x * blockDim.x;
    for (int e = blockIdx.x * blockDim.x + threadIdx.x; e < NEDGES; e += stride)
        atomicAdd(&g_cnt[idx[e]], 1);
}

// block-level exclusive scan, coalesced; writes local prefixes + block totals
__global__ void __launch_bounds__(SCAN_BLK) scan1_kernel() {
    __shared__ int warp_sums[32];
    const int b = blockIdx.x, t = threadIdx.x;
    const int i = b * SCAN_BLK + t;
    const int lane = t & 31, wid = t >> 5;
    int v = (i < NNODES) ? g_cnt[i] : 0;
    int s = v;
#pragma unroll
    for (int o = 1; o < 32; o <<= 1) {
        int u = __shfl_up_sync(0xFFFFFFFFu, s, o);
        if (lane >= o) s += u;
    }
    if (lane == 31) warp_sums[wid] = s;
    __syncthreads();
    if (wid == 0) {
        int ws = warp_sums[lane];
#pragma unroll
        for (int o = 1; o < 32; o <<= 1) {
            int u = __shfl_up_sync(0xFFFFFFFFu, ws, o);
            if (lane >= o) ws += u;
        }
        warp_sums[lane] = ws;
    }
    __syncthreads();
    int excl = s - v + (wid > 0 ? warp_sums[wid - 1] : 0);
    if (i < NNODES) g_rowptr[i] = excl;
    if (t == SCAN_BLK - 1) g_bsum[b] = excl + v;
}

__global__ void scan2_kernel() {   // 1 block, 64 threads over SCAN_NB=49 sums
    const int t = threadIdx.x;
    const int lane = t & 31, wid = t >> 5;
    __shared__ int wsum[2];
    int v = (t < SCAN_NB) ? g_bsum[t] : 0;
    int s = v;
#pragma unroll
    for (int o = 1; o < 32; o <<= 1) {
        int u = __shfl_up_sync(0xFFFFFFFFu, s, o);
        if (lane >= o) s += u;
    }
    if (lane == 31) wsum[wid] = s;
    __syncthreads();
    int excl = s - v + (wid ? wsum[0] : 0);
    if (t < SCAN_NB) g_boff[t] = excl;
    if (t == SCAN_NB - 1) g_rowptr[NNODES] = excl + v;
}

__global__ void scan3_kernel() {
    int i = blockIdx.x * blockDim.x + threadIdx.x;
    if (i < NNODES) g_rowptr[i] += g_boff[i >> 10];   // SCAN_BLK = 1024
}

__global__ void fill_kernel(const int* __restrict__ idx, const float* __restrict__ val) {
    int stride = gridDim.x * blockDim.x;
    for (int e = blockIdx.x * blockDim.x + threadIdx.x; e < NEDGES; e += stride) {
        int r = idx[e];
        int pos = g_rowptr[r] + atomicAdd(&g_cnt[r], 1);
        g_ecol[pos] = idx[NEDGES + e];
        g_eval[pos] = val[e];
    }
}

// ---------------- TF32 mma.sync GEMM: C = act(A @ B + bias) ----------------
// A: [M,K] row-major, B: [K,Nc] row-major, C: [M,Nc]
#define GBM 128
#define GBN 64
#define GBK 32

__device__ __forceinline__ unsigned f2tf(float x) {
    unsigned u;
    asm("cvt.rna.tf32.f32 %0, %1;" : "=r"(u) : "f"(x));
    return u;
}

__global__ void __launch_bounds__(256) mma_gemm_kernel(
    const float* __restrict__ A, const float* __restrict__ B, float* __restrict__ C,
    int M, int K, int Nc, const float* __restrict__ bias, int act)
{
    __shared__ unsigned As[GBM][GBK + 1];   // row stride 33
    __shared__ unsigned Bs[GBK][GBN + 1];   // row stride 65
    const int tid  = threadIdx.x;
    const int row0 = blockIdx.y * GBM;
    const int col0 = blockIdx.x * GBN;
    const int lane = tid & 31;
    const int wid  = tid >> 5;
    const int wm   = (wid & 3) * 32;    // warp m-offset
    const int wn   = (wid >> 2) * 32;   // warp n-offset
    const int grp  = lane >> 2;
    const int tig  = lane & 3;

    float c[2][4][4];
#pragma unroll
    for (int mi = 0; mi < 2; mi++)
#pragma unroll
        for (int ni = 0; ni < 4; ni++)
#pragma unroll
            for (int e = 0; e < 4; e++) c[mi][ni][e] = 0.f;

    const bool fullM = (row0 + GBM <= M);
    const bool fullN = (col0 + GBN <= Nc);

    for (int k0 = 0; k0 < K; k0 += GBK) {
        const bool fullK = (k0 + GBK <= K);
        // ---- load A tile 128x32 ----
        if (fullK && fullM) {
            int r  = tid >> 3;           // 0..31
            int cc = (tid & 7) * 4;
#pragma unroll
            for (int p = 0; p < 4; p++) {
                const float4 v = *(const float4*)&A[(size_t)(row0 + r + p * 32) * K + k0 + cc];
                As[r + p * 32][cc + 0] = f2tf(v.x);
                As[r + p * 32][cc + 1] = f2tf(v.y);
                As[r + p * 32][cc + 2] = f2tf(v.z);
                As[r + p * 32][cc + 3] = f2tf(v.w);
            }
        } else {
#pragma unroll
            for (int l = 0; l < 16; l++) {
                int idx = tid + l * 256;
                int r = idx >> 5, cc = idx & 31;
                int gr = row0 + r, gk = k0 + cc;
                float v = (gr < M && gk < K) ? A[(size_t)gr * K + gk] : 0.f;
                As[r][cc] = f2tf(v);
            }
        }
        // ---- load B tile 32x64 ----
        if (fullK && fullN) {
            int r  = tid >> 4;           // 0..15
            int cc = (tid & 15) * 4;
#pragma unroll
            for (int p = 0; p < 2; p++) {
                const float4 v = *(const float4*)&B[(size_t)(k0 + r + p * 16) * Nc + col0 + cc];
                Bs[r + p * 16][cc + 0] = f2tf(v.x);
                Bs[r + p * 16][cc + 1] = f2tf(v.y);
                Bs[r + p * 16][cc + 2] = f2tf(v.z);
                Bs[r + p * 16][cc + 3] = f2tf(v.w);
            }
        } else {
#pragma unroll
            for (int l = 0; l < 8; l++) {
                int idx = tid + l * 256;
                int r = idx >> 6, cc = idx & 63;
                int gk = k0 + r, gc = col0 + cc;
                float v = (gk < K && gc < Nc) ? B[(size_t)gk * Nc + gc] : 0.f;
                Bs[r][cc] = f2tf(v);
            }
        }
        __syncthreads();
#pragma unroll
        for (int kk = 0; kk < GBK; kk += 8) {
            unsigned a[2][4], b[4][2];
#pragma unroll
            for (int mi = 0; mi < 2; mi++) {
                int r = wm + mi * 16 + grp;
                a[mi][0] = As[r][kk + tig];
                a[mi][1] = As[r + 8][kk + tig];
                a[mi][2] = As[r][kk + tig + 4];
                a[mi][3] = As[r + 8][kk + tig + 4];
            }
#pragma unroll
            for (int ni = 0; ni < 4; ni++) {
                int cn = wn + ni * 8 + grp;
                b[ni][0] = Bs[kk + tig][cn];
                b[ni][1] = Bs[kk + tig + 4][cn];
            }
#pragma unroll
            for (int mi = 0; mi < 2; mi++)
#pragma unroll
                for (int ni = 0; ni < 4; ni++)
                    asm volatile(
                        "mma.sync.aligned.m16n8k8.row.col.f32.tf32.tf32.f32 "
                        "{%0,%1,%2,%3}, {%4,%5,%6,%7}, {%8,%9}, {%0,%1,%2,%3};"
                        : "+f"(c[mi][ni][0]), "+f"(c[mi][ni][1]),
                          "+f"(c[mi][ni][2]), "+f"(c[mi][ni][3])
                        : "r"(a[mi][0]), "r"(a[mi][1]), "r"(a[mi][2]), "r"(a[mi][3]),
                          "r"(b[ni][0]), "r"(b[ni][1]));
        }
        __syncthreads();
    }
    // ---- epilogue ----
#pragma unroll
    for (int mi = 0; mi < 2; mi++)
#pragma unroll
        for (int ni = 0; ni < 4; ni++)
#pragma unroll
            for (int e = 0; e < 4; e++) {
                int r  = row0 + wm + mi * 16 + grp + ((e >= 2) ? 8 : 0);
                int cn = col0 + wn + ni * 8 + tig * 2 + (e & 1);
                if (r < M && cn < Nc) {
                    float v = c[mi][ni][e];
                    if (bias) v += bias[cn];
                    if (act)  v = (v > 0.f) ? v : 0.01f * v;   // leaky_relu 0.01
                    C[(size_t)r * Nc + cn] = v;
                }
            }
}

// ---------------- SpMM1 fused: spmm + bias + sigmoid + mean(h_sec)*h_thi concat ----------------
__global__ void __launch_bounds__(224) spmm1_kernel(float* __restrict__ low_out) {
    const int i = blockIdx.x, t = threadIdx.x;
    const int s0 = g_rowptr[i], s1 = g_rowptr[i + 1];
    __shared__ int   sc[64];
    __shared__ float sv[64];
    float acc = 0.f;
    for (int base = s0; base < s1; base += 64) {
        int n = min(64, s1 - base);
        for (int l = t; l < n; l += 224) { sc[l] = g_ecol[base + l]; sv[l] = g_eval[base + l]; }
        __syncthreads();
        if (t < F1) {
            for (int e = 0; e < n; e++)
                acc += sv[e] * g_H[(size_t)sc[e] * F1 + t];
        }
        __syncthreads();
    }
    float v = 0.f;
    if (t < F1) {
        float z = acc + g_bc1[t];
        v = 1.f / (1.f + __expf(-z));
    }
    __shared__ float red[256];
    red[t] = (t >= 64 && t < 132) ? v : 0.f;   // h_sec block
    if (t < 32) red[224 + t] = 0.f;
    __syncthreads();
    for (int s = 128; s > 0; s >>= 1) {
        if (t < s) red[t] += red[t + s];
        __syncthreads();
    }
    float mean = red[0] * (1.f / 68.f);
    if (t < F1) {
        float lr = (t < 132) ? v : mean * v;   // [h_fir, h_sec, mean(h_sec)*h_thi]
        low_out[(size_t)i * F1 + t] = lr;
    }
}

// ---------------- SpMM2: spmm + bias -> h_fou (scratch), h_fiv (out) ----------------
__global__ void __launch_bounds__(288) spmm2_kernel(float* __restrict__ fiv_out) {
    const int i = blockIdx.x, t = threadIdx.x;
    const int s0 = g_rowptr[i], s1 = g_rowptr[i + 1];
    __shared__ int   sc[64];
    __shared__ float sv[64];
    float acc = 0.f;
    for (int base = s0; base < s1; base += 64) {
        int n = min(64, s1 - base);
        for (int l = t; l < n; l += 288) { sc[l] = g_ecol[base + l]; sv[l] = g_eval[base + l]; }
        __syncthreads();
        if (t < F2) {
            for (int e = 0; e < n; e++)
                acc += sv[e] * g_H[(size_t)sc[e] * F2 + t];
        }
        __syncthreads();
    }
    if (t < F2) {
        float z = acc + g_bc2[t];
        if (t < 132) g_fou[(size_t)i * 132 + t] = z;
        else         fiv_out[(size_t)i * 128 + (t - 132)] = z;
    }
}

// ---------------- final: low = mean(lr)*lr + lr ; f3 = (mlp + fou)/2 ----------------
__global__ void __launch_bounds__(384) final_kernel(const float* __restrict__ low,
                                                    const float* __restrict__ mlp,
                                                    float* __restrict__ fin) {
    const int i = blockIdx.x, t = threadIdx.x;
    float lr = (t < 204) ? low[(size_t)i * 204 + t] : 0.f;
    __shared__ float red[512];
    red[t] = (t < 204) ? lr : 0.f;
    if (t < 128) red[384 + t] = 0.f;
    __syncthreads();
    for (int s = 256; s > 0; s >>= 1) {
        if (t < s) red[t] += red[t + s];
        __syncthreads();
    }
    float mean = red[0] * (1.f / 204.f);
    if (t < 204) {
        fin[(size_t)i * 336 + t] = mean * lr + lr;
    } else if (t < 336) {
        int j = t - 204;
        fin[(size_t)i * 336 + t] = 0.5f * (mlp[(size_t)i * 132 + j] + g_fou[(size_t)i * 132 + j]);
    }
}

// ---------------- launch ----------------
extern "C" void kernel_launch(void* const* d_in, const int* in_sizes, int n_in,
                              void* d_out, int out_size) {
    const float* x  = (const float*)d_in[0];
    const int*   a1 = (const int*)d_in[1];
    const float* v1 = (const float*)d_in[2];
    const float* y  = (const float*)d_in[3];
    const int*   a2 = (const int*)d_in[4];
    const float* v2 = (const float*)d_in[5];
    const float* W1 = (const float*)d_in[6];
    const float* b1 = (const float*)d_in[7];
    const float* W2 = (const float*)d_in[8];
    const float* b2 = (const float*)d_in[9];
    const float* W3 = (const float*)d_in[10];
    const float* b3 = (const float*)d_in[11];
    const float* W4 = (const float*)d_in[12];
    const float* b4 = (const float*)d_in[13];
    const float* W5 = (const float*)d_in[14];
    const float* b5 = (const float*)d_in[15];
    const float* Wm = (const float*)d_in[16];
    const float* bm = (const float*)d_in[17];
    float* out = (float*)d_out;

    void* p;
    float *dH, *dWc1, *dWc2;
    cudaGetSymbolAddress(&p, g_H);   dH   = (float*)p;
    cudaGetSymbolAddress(&p, g_Wc1); dWc1 = (float*)p;
    cudaGetSymbolAddress(&p, g_Wc2); dWc2 = (float*)p;

    const size_t N = NNODES;
    const size_t O_XLOW = 0;
    const size_t O_YLOW = N * 204;
    const size_t O_XFIN = 2 * N * 204;
    const size_t O_YFIN = 2 * N * 204 + N * 336;
    const size_t O_XFIV = 2 * N * 204 + 2 * N * 336;
    const size_t O_XMLP = O_XFIV + N * 128;
    const size_t O_YFIV = O_XMLP + N * 132;
    const size_t O_YMLP = O_YFIV + N * 128;

    pack_kernel<<<(FIN0 * F1 + F1 * F2 + 255) / 256, 256>>>(W1, b1, W2, b2, W3, b3, W4, b4, W5, b5);

    const int MROWBLKS = (NNODES + GBM - 1) / GBM;   // 391

    for (int b = 0; b < 2; b++) {
        const float* X   = b ? y  : x;
        const int*   adj = b ? a2 : a1;
        const float* ev  = b ? v2 : v1;
        float* lowo = out + (b ? O_YLOW : O_XLOW);
        float* fino = out + (b ? O_YFIN : O_XFIN);
        float* fivo = out + (b ? O_YFIV : O_XFIV);
        float* mlpo = out + (b ? O_YMLP : O_XMLP);

        // CSR build
        zero_cnt_kernel<<<(NNODES + 255) / 256, 256>>>();
        hist_kernel<<<1024, 256>>>(adj);
        scan1_kernel<<<SCAN_NB, SCAN_BLK>>>();
        scan2_kernel<<<1, 64>>>();
        scan3_kernel<<<(NNODES + 255) / 256, 256>>>();
        zero_cnt_kernel<<<(NNODES + 255) / 256, 256>>>();
        fill_kernel<<<1024, 256>>>(adj, ev);

        // H1 = X @ [W1|W2|W3]
        mma_gemm_kernel<<<dim3(4, MROWBLKS), 256>>>(X, dWc1, dH, NNODES, 128, 204, nullptr, 0);
        // low_result = fused spmm+sigmoid+concat
        spmm1_kernel<<<NNODES, 224>>>(lowo);
        // G2 = low_result @ [W4|W5]
        mma_gemm_kernel<<<dim3(5, MROWBLKS), 256>>>(lowo, dWc2, dH, NNODES, 204, 260, nullptr, 0);
        // spmm -> h_fou (scratch) + h_fiv (output)
        spmm2_kernel<<<NNODES, 288>>>(fivo);
        // h_mlp = leaky_relu(h_fiv @ Wm + bm)
        mma_gemm_kernel<<<dim3(3, MROWBLKS), 256>>>(fivo, Wm, mlpo, NNODES, 128, 132, bm, 1);
        // final
        final_kernel<<<NNODES, 384>>>(lowo, mlpo, fino);
    }
}

// round 4
// speedup vs baseline: 1.8192x; 1.6604x over previous
#include <cuda_runtime.h>
#include <cuda_fp16.h>

#define NNODES 50000
#define NEDGES 800000
#define FIN0   128
#define F1     204      // 64+68+72
#define F2     260      // 132+128
#define S4_1   51       // F1/4 (4-feature groups)
#define S4_2   65       // F2/4
#define SCAN_BLK 1024
#define SCAN_NB  49

// ---------------- device scratch ----------------
__device__ __half g_Hh[2][(size_t)NNODES * F2];   // fp16 GEMM outputs (gather operand)
__device__ float  g_fou[2][(size_t)NNODES * 132];
__device__ float  g_Wc1[FIN0 * F1];
__device__ float  g_bc1[F1];
__device__ float  g_Wc2[F1 * F2];
__device__ float  g_bc2[F2];
__device__ int    g_rowptr[2][NNODES + 2];
__device__ int    g_cnt[2][NNODES];
__device__ int    g_boff[2][64];
__device__ uint2  g_edge[2][NEDGES];              // {col, valbits}

// ---------------- pack weights + zero counters ----------------
__global__ void pack_kernel(const float* __restrict__ W1, const float* __restrict__ b1,
                            const float* __restrict__ W2, const float* __restrict__ b2,
                            const float* __restrict__ W3, const float* __restrict__ b3,
                            const float* __restrict__ W4, const float* __restrict__ b4,
                            const float* __restrict__ W5, const float* __restrict__ b5) {
    int i = blockIdx.x * blockDim.x + threadIdx.x;
    if (i < FIN0 * F1) {
        int k = i / F1, c = i % F1;
        g_Wc1[i] = (c < 64) ? W1[k * 64 + c]
                 : (c < 132) ? W2[k * 68 + (c - 64)]
                             : W3[k * 72 + (c - 132)];
    }
    int j = i - FIN0 * F1;
    if (j >= 0 && j < F1 * F2) {
        int k = j / F2, c = j % F2;
        g_Wc2[j] = (c < 132) ? W4[k * 132 + c] : W5[k * 128 + (c - 132)];
    }
    if (i < F1) g_bc1[i] = (i < 64) ? b1[i] : (i < 132) ? b2[i - 64] : b3[i - 132];
    if (i < F2) g_bc2[i] = (i < 132) ? b4[i] : b5[i - 132];
    if (i < NNODES) { g_cnt[0][i] = 0; g_cnt[1][i] = 0; }
    if (i < 64)     { g_boff[0][i] = 0; g_boff[1][i] = 0; }
}

// ---------------- CSR build (int32 idx: row=idx[e], col=idx[E+e]) ----------------
__global__ void hist_kernel(const int* __restrict__ i1, const int* __restrict__ i2) {
    const int br = blockIdx.y;
    const int* idx = br ? i2 : i1;
    int* cnt = g_cnt[br];
    int stride = gridDim.x * blockDim.x;
    for (int e = blockIdx.x * blockDim.x + threadIdx.x; e < NEDGES; e += stride)
        atomicAdd(&cnt[idx[e]], 1);
}

__global__ void __launch_bounds__(SCAN_BLK) scan1_kernel() {
    __shared__ int warp_sums[32];
    __shared__ int sTot;
    const int br = blockIdx.y, b = blockIdx.x, t = threadIdx.x;
    const int i = b * SCAN_BLK + t;
    const int lane = t & 31, wid = t >> 5;
    int v = (i < NNODES) ? g_cnt[br][i] : 0;
    int s = v;
#pragma unroll
    for (int o = 1; o < 32; o <<= 1) {
        int u = __shfl_up_sync(0xFFFFFFFFu, s, o);
        if (lane >= o) s += u;
    }
    if (lane == 31) warp_sums[wid] = s;
    __syncthreads();
    if (wid == 0) {
        int ws = warp_sums[lane];
#pragma unroll
        for (int o = 1; o < 32; o <<= 1) {
            int u = __shfl_up_sync(0xFFFFFFFFu, ws, o);
            if (lane >= o) ws += u;
        }
        warp_sums[lane] = ws;
    }
    __syncthreads();
    int excl = s - v + (wid > 0 ? warp_sums[wid - 1] : 0);
    if (i <= NNODES) g_rowptr[br][i] = excl;
    if (t == SCAN_BLK - 1) sTot = excl + v;
    __syncthreads();
    int total = sTot;
    if (t > b && t < SCAN_NB) atomicAdd(&g_boff[br][t], total);
}

__global__ void fill_kernel(const int* __restrict__ i1, const float* __restrict__ v1,
                            const int* __restrict__ i2, const float* __restrict__ v2) {
    const int br = blockIdx.y;
    const int*   idx = br ? i2 : i1;
    const float* val = br ? v2 : v1;
    int* cnt = g_cnt[br];
    const int* rp = g_rowptr[br];
    const int* bo = g_boff[br];
    uint2* edge = g_edge[br];
    int stride = gridDim.x * blockDim.x;
    for (int e = blockIdx.x * blockDim.x + threadIdx.x; e < NEDGES; e += stride) {
        int r = idx[e];
        int slot = atomicSub(&cnt[r], 1) - 1;
        int pos = rp[r] + bo[r >> 10] + slot;
        edge[pos] = make_uint2((unsigned)idx[NEDGES + e], __float_as_uint(val[e]));
    }
}

// ---------------- TF32 mma GEMM: C = act(A @ B + bias), branch via blockIdx.z ----------------
#define GBM 128
#define GBN 64
#define GBK 32

__device__ __forceinline__ unsigned f2tf(float x) {
    unsigned u;
    asm("cvt.rna.tf32.f32 %0, %1;" : "=r"(u) : "f"(x));
    return u;
}

template<bool OUTH, bool ACT>
__global__ void __launch_bounds__(256) mma_gemm_kernel(
    const float* __restrict__ A0, const float* __restrict__ A1,
    void* __restrict__ C0v, void* __restrict__ C1v,
    int M, int K, int Nc, const float* __restrict__ bias)
{
    const float* A = blockIdx.z ? A1 : A0;
    void* Cv = blockIdx.z ? C1v : C0v;
    __shared__ unsigned As[GBM][GBK + 1];
    __shared__ unsigned Bs[GBK][GBN + 1];
    const int tid  = threadIdx.x;
    const int row0 = blockIdx.y * GBM;
    const int col0 = blockIdx.x * GBN;
    const int lane = tid & 31;
    const int wid  = tid >> 5;
    const int wm   = (wid & 3) * 32;
    const int wn   = (wid >> 2) * 32;
    const int grp  = lane >> 2;
    const int tig  = lane & 3;
    const float* B = (K == FIN0 && Nc == F1) ? g_Wc1 : g_Wc2;   // overridden below for mlp
    // NOTE: for the MLP GEMM we pass B via bias-independent trick: see launch (we reuse A1 slot? no)
    // -> B pointer passed through C1v? keep simple: B chosen by a constant; mlp uses g_Wc2? NO.
    // B is provided explicitly through a __grid_constant__-free param:
    // (resolved by passing B in A1 when gridDim.z==2 is impossible) -- see Bp param below.
    (void)B;
    const float* Bp = nullptr;
    // Bp set via template-less trick is ugly; instead B passed as last arg:
    // -- replaced below by real parameter --
    asm volatile("" ::: "memory");
    // (actual B comes from the extra parameter)
    extern __shared__ int _dummy[];
    (void)_dummy; (void)Bp;
    // This placeholder is never compiled-in: real implementation in mma_gemm_kernel2.
}

// real GEMM (B passed explicitly)
template<bool OUTH, bool ACT>
__global__ void __launch_bounds__(256) gemm_k(
    const float* __restrict__ A0, const float* __restrict__ A1,
    const float* __restrict__ B,
    void* __restrict__ C0v, void* __restrict__ C1v,
    int M, int K, int Nc, const float* __restrict__ bias)
{
    const float* A = blockIdx.z ? A1 : A0;
    void* Cv = blockIdx.z ? C1v : C0v;
    __shared__ unsigned As[GBM][GBK + 1];
    __shared__ unsigned Bs[GBK][GBN + 1];
    const int tid  = threadIdx.x;
    const int row0 = blockIdx.y * GBM;
    const int col0 = blockIdx.x * GBN;
    const int lane = tid & 31;
    const int wid  = tid >> 5;
    const int wm   = (wid & 3) * 32;
    const int wn   = (wid >> 2) * 32;
    const int grp  = lane >> 2;
    const int tig  = lane & 3;

    float c[2][4][4];
#pragma unroll
    for (int mi = 0; mi < 2; mi++)
#pragma unroll
        for (int ni = 0; ni < 4; ni++)
#pragma unroll
            for (int e = 0; e < 4; e++) c[mi][ni][e] = 0.f;

    const bool fullM = (row0 + GBM <= M);
    const bool fullN = (col0 + GBN <= Nc);

    for (int k0 = 0; k0 < K; k0 += GBK) {
        const bool fullK = (k0 + GBK <= K);
        if (fullK && fullM) {
            int r  = tid >> 3;
            int cc = (tid & 7) * 4;
#pragma unroll
            for (int p = 0; p < 4; p++) {
                const float4 v = *(const float4*)&A[(size_t)(row0 + r + p * 32) * K + k0 + cc];
                As[r + p * 32][cc + 0] = f2tf(v.x);
                As[r + p * 32][cc + 1] = f2tf(v.y);
                As[r + p * 32][cc + 2] = f2tf(v.z);
                As[r + p * 32][cc + 3] = f2tf(v.w);
            }
        } else {
#pragma unroll
            for (int l = 0; l < 16; l++) {
                int idx = tid + l * 256;
                int r = idx >> 5, cc = idx & 31;
                int gr = row0 + r, gk = k0 + cc;
                float v = (gr < M && gk < K) ? A[(size_t)gr * K + gk] : 0.f;
                As[r][cc] = f2tf(v);
            }
        }
        if (fullK && fullN) {
            int r  = tid >> 4;
            int cc = (tid & 15) * 4;
#pragma unroll
            for (int p = 0; p < 2; p++) {
                const float4 v = *(const float4*)&B[(size_t)(k0 + r + p * 16) * Nc + col0 + cc];
                Bs[r + p * 16][cc + 0] = f2tf(v.x);
                Bs[r + p * 16][cc + 1] = f2tf(v.y);
                Bs[r + p * 16][cc + 2] = f2tf(v.z);
                Bs[r + p * 16][cc + 3] = f2tf(v.w);
            }
        } else {
#pragma unroll
            for (int l = 0; l < 8; l++) {
                int idx = tid + l * 256;
                int r = idx >> 6, cc = idx & 63;
                int gk = k0 + r, gc = col0 + cc;
                float v = (gk < K && gc < Nc) ? B[(size_t)gk * Nc + gc] : 0.f;
                Bs[r][cc] = f2tf(v);
            }
        }
        __syncthreads();
#pragma unroll
        for (int kk = 0; kk < GBK; kk += 8) {
            unsigned a[2][4], b[4][2];
#pragma unroll
            for (int mi = 0; mi < 2; mi++) {
                int r = wm + mi * 16 + grp;
                a[mi][0] = As[r][kk + tig];
                a[mi][1] = As[r + 8][kk + tig];
                a[mi][2] = As[r][kk + tig + 4];
                a[mi][3] = As[r + 8][kk + tig + 4];
            }
#pragma unroll
            for (int ni = 0; ni < 4; ni++) {
                int cn = wn + ni * 8 + grp;
                b[ni][0] = Bs[kk + tig][cn];
                b[ni][1] = Bs[kk + tig + 4][cn];
            }
#pragma unroll
            for (int mi = 0; mi < 2; mi++)
#pragma unroll
                for (int ni = 0; ni < 4; ni++)
                    asm volatile(
                        "mma.sync.aligned.m16n8k8.row.col.f32.tf32.tf32.f32 "
                        "{%0,%1,%2,%3}, {%4,%5,%6,%7}, {%8,%9}, {%0,%1,%2,%3};"
                        : "+f"(c[mi][ni][0]), "+f"(c[mi][ni][1]),
                          "+f"(c[mi][ni][2]), "+f"(c[mi][ni][3])
                        : "r"(a[mi][0]), "r"(a[mi][1]), "r"(a[mi][2]), "r"(a[mi][3]),
                          "r"(b[ni][0]), "r"(b[ni][1]));
        }
        __syncthreads();
    }
    // epilogue: pairwise stores (cn even)
#pragma unroll
    for (int mi = 0; mi < 2; mi++)
#pragma unroll
        for (int ni = 0; ni < 4; ni++)
#pragma unroll
            for (int h = 0; h < 2; h++) {
                int r  = row0 + wm + mi * 16 + grp + h * 8;
                int cn = col0 + wn + ni * 8 + tig * 2;
                if (r < M && cn < Nc) {
                    float v0 = c[mi][ni][h * 2 + 0];
                    float v1 = c[mi][ni][h * 2 + 1];
                    if (bias) { v0 += bias[cn]; v1 += bias[cn + 1]; }
                    if (ACT) {
                        v0 = (v0 > 0.f) ? v0 : 0.01f * v0;
                        v1 = (v1 > 0.f) ? v1 : 0.01f * v1;
                    }
                    if (OUTH) {
                        __half2* C = (__half2*)Cv;
                        C[((size_t)r * Nc + cn) >> 1] = __floats2half2_rn(v0, v1);
                    } else {
                        float2* C = (float2*)Cv;
                        C[((size_t)r * Nc + cn) >> 1] = make_float2(v0, v1);
                    }
                }
            }
}

// ---------------- helpers ----------------
__device__ __forceinline__ float4 sig4(float4 z) {
    float4 r;
    r.x = 1.f / (1.f + __expf(-z.x));
    r.y = 1.f / (1.f + __expf(-z.y));
    r.z = 1.f / (1.f + __expf(-z.z));
    r.w = 1.f / (1.f + __expf(-z.w));
    return r;
}
__device__ __forceinline__ void fma4h(float4& a, float v, uint2 h) {
    float2 lo = __half22float2(*(const __half2*)&h.x);
    float2 hi = __half22float2(*(const __half2*)&h.y);
    a.x += v * lo.x; a.y += v * lo.y; a.z += v * hi.x; a.w += v * hi.y;
}

// ---------------- SpMM1 (warp per node): sigmoid + mean(h_sec)*h_thi concat ----------------
__global__ void __launch_bounds__(256) spmm1_kernel(float* __restrict__ low_x,
                                                    float* __restrict__ low_y) {
    const int lane = threadIdx.x & 31;
    const int i = blockIdx.x * 8 + (threadIdx.x >> 5);
    if (i >= NNODES) return;
    const int br = blockIdx.y;
    const int* rp = g_rowptr[br];
    const int* bo = g_boff[br];
    const uint2* edge = g_edge[br];
    const uint2* H2 = (const uint2*)g_Hh[br];
    float* low = br ? low_y : low_x;

    const int s0 = rp[i] + bo[i >> 10];
    const int s1 = rp[i + 1] + bo[(i + 1) >> 10];
    float4 a0 = {0, 0, 0, 0}, a1 = {0, 0, 0, 0};

    for (int e0 = s0; e0 < s1; e0 += 32) {
        int e = e0 + lane;
        uint2 ev = (e < s1) ? edge[e] : make_uint2(0, 0);
        int n = min(32, s1 - e0);
#pragma unroll 4
        for (int j = 0; j < n; j++) {
            int cc  = __shfl_sync(0xFFFFFFFFu, (int)ev.x, j);
            float v = __uint_as_float(__shfl_sync(0xFFFFFFFFu, ev.y, j));
            const uint2* row = H2 + (size_t)cc * S4_1;
            fma4h(a0, v, row[lane]);
            if (lane < S4_1 - 32) fma4h(a1, v, row[32 + lane]);
        }
    }
    const float4* b4 = (const float4*)g_bc1;
    float4 v0 = sig4(make_float4(a0.x + b4[lane].x, a0.y + b4[lane].y,
                                 a0.z + b4[lane].z, a0.w + b4[lane].w));
    float4 v1 = {0, 0, 0, 0};
    if (lane < S4_1 - 32) {
        float4 bb = b4[32 + lane];
        v1 = sig4(make_float4(a1.x + bb.x, a1.y + bb.y, a1.z + bb.z, a1.w + bb.w));
    }
    // mean over h_sec = features 64..131 -> q 16..32
    float part = 0.f;
    if (lane >= 16) part = v0.x + v0.y + v0.z + v0.w;
    if (lane == 0)  part += v1.x + v1.y + v1.z + v1.w;   // q=32 (f 128..131)
#pragma unroll
    for (int o = 16; o > 0; o >>= 1) part += __shfl_xor_sync(0xFFFFFFFFu, part, o);
    const float mean = part * (1.f / 68.f);

    float4* lw = (float4*)(low + (size_t)i * F1);
    lw[lane] = v0;                                        // q 0..31 all < 33 -> plain
    if (lane < S4_1 - 32) {
        float4 w = (lane == 0) ? v1                       // q=32: f<132 -> plain
                 : make_float4(mean * v1.x, mean * v1.y, mean * v1.z, mean * v1.w);
        lw[32 + lane] = w;
    }
}

// ---------------- SpMM2 (warp per node): +bias -> h_fou (scratch), h_fiv (out) ----------------
__global__ void __launch_bounds__(256) spmm2_kernel(float* __restrict__ fiv_x,
                                                    float* __restrict__ fiv_y) {
    const int lane = threadIdx.x & 31;
    const int i = blockIdx.x * 8 + (threadIdx.x >> 5);
    if (i >= NNODES) return;
    const int br = blockIdx.y;
    const int* rp = g_rowptr[br];
    const int* bo = g_boff[br];
    const uint2* edge = g_edge[br];
    const uint2* H2 = (const uint2*)g_Hh[br];
    float* fiv = br ? fiv_y : fiv_x;
    float4* fou4 = (float4*)g_fou[br];

    const int s0 = rp[i] + bo[i >> 10];
    const int s1 = rp[i + 1] + bo[(i + 1) >> 10];
    float4 a0 = {0, 0, 0, 0}, a1 = {0, 0, 0, 0}, a2 = {0, 0, 0, 0};

    for (int e0 = s0; e0 < s1; e0 += 32) {
        int e = e0 + lane;
        uint2 ev = (e < s1) ? edge[e] : make_uint2(0, 0);
        int n = min(32, s1 - e0);
#pragma unroll 4
        for (int j = 0; j < n; j++) {
            int cc  = __shfl_sync(0xFFFFFFFFu, (int)ev.x, j);
            float v = __uint_as_float(__shfl_sync(0xFFFFFFFFu, ev.y, j));
            const uint2* row = H2 + (size_t)cc * S4_2;
            fma4h(a0, v, row[lane]);
            fma4h(a1, v, row[32 + lane]);                 // q 32..63, all < 65
            if (lane == 0) fma4h(a2, v, row[64]);         // q = 64
        }
    }
    const float4* b4 = (const float4*)g_bc2;
    float4 bb0 = b4[lane], bb1 = b4[32 + lane];
    float4 z0 = make_float4(a0.x + bb0.x, a0.y + bb0.y, a0.z + bb0.z, a0.w + bb0.w);
    float4 z1 = make_float4(a1.x + bb1.x, a1.y + bb1.y, a1.z + bb1.z, a1.w + bb1.w);
    float4* fv4 = (float4*)(fiv + (size_t)i * 128);
    fou4[(size_t)i * 33 + lane] = z0;                     // q 0..31 (f<132)
    if (lane == 0) {
        fou4[(size_t)i * 33 + 32] = z1;                   // q=32 (f 128..131)
        float4 bb2 = b4[64];
        fv4[31] = make_float4(a2.x + bb2.x, a2.y + bb2.y, a2.z + bb2.z, a2.w + bb2.w);  // q=64
    } else {
        fv4[lane - 1] = z1;                               // q 33..63 -> fiv 0..30
    }
}

// ---------------- final (warp per node): low = (1+mean)*lr ; f3 = (mlp+fou)/2 ----------------
__global__ void __launch_bounds__(256) final_kernel(const float* __restrict__ low_x,
                                                    const float* __restrict__ low_y,
                                                    const float* __restrict__ mlp_x,
                                                    const float* __restrict__ mlp_y,
                                                    float* __restrict__ fin_x,
                                                    float* __restrict__ fin_y) {
    const int lane = threadIdx.x & 31;
    const int i = blockIdx.x * 8 + (threadIdx.x >> 5);
    if (i >= NNODES) return;
    const int br = blockIdx.y;
    const float4* lw = (const float4*)((br ? low_y : low_x) + (size_t)i * F1);
    const float4* mp = (const float4*)((br ? mlp_y : mlp_x) + (size_t)i * 132);
    const float4* fo = (const float4*)g_fou[br] + (size_t)i * 33;
    float4* fn = (float4*)((br ? fin_y : fin_x) + (size_t)i * 336);

    float4 l0 = lw[lane];
    float4 l1 = {0, 0, 0, 0};
    if (lane < S4_1 - 32) l1 = lw[32 + lane];
    float part = l0.x + l0.y + l0.z + l0.w + l1.x + l1.y + l1.z + l1.w;
#pragma unroll
    for (int o = 16; o > 0; o >>= 1) part += __shfl_xor_sync(0xFFFFFFFFu, part, o);
    const float s = 1.f + part * (1.f / 204.f);

    fn[lane] = make_float4(s * l0.x, s * l0.y, s * l0.z, s * l0.w);
    if (lane < S4_1 - 32)
        fn[32 + lane] = make_float4(s * l1.x, s * l1.y, s * l1.z, s * l1.w);

    float4 m = mp[lane], f = fo[lane];
    fn[51 + lane] = make_float4(0.5f * (m.x + f.x), 0.5f * (m.y + f.y),
                                0.5f * (m.z + f.z), 0.5f * (m.w + f.w));
    if (lane == 0) {
        float4 m2 = mp[32], f2 = fo[32];
        fn[51 + 32] = make_float4(0.5f * (m2.x + f2.x), 0.5f * (m2.y + f2.y),
                                  0.5f * (m2.z + f2.z), 0.5f * (m2.w + f2.w));
    }
}

// ---------------- launch ----------------
extern "C" void kernel_launch(void* const* d_in, const int* in_sizes, int n_in,
                              void* d_out, int out_size) {
    const float* x  = (const float*)d_in[0];
    const int*   a1 = (const int*)d_in[1];
    const float* v1 = (const float*)d_in[2];
    const float* y  = (const float*)d_in[3];
    const int*   a2 = (const int*)d_in[4];
    const float* v2 = (const float*)d_in[5];
    const float* W1 = (const float*)d_in[6];
    const float* b1 = (const float*)d_in[7];
    const float* W2 = (const float*)d_in[8];
    const float* b2 = (const float*)d_in[9];
    const float* W3 = (const float*)d_in[10];
    const float* b3 = (const float*)d_in[11];
    const float* W4 = (const float*)d_in[12];
    const float* b4 = (const float*)d_in[13];
    const float* W5 = (const float*)d_in[14];
    const float* b5 = (const float*)d_in[15];
    const float* Wm = (const float*)d_in[16];
    const float* bm = (const float*)d_in[17];
    float* out = (float*)d_out;

    void* p;
    __half *dH0, *dH1;
    float *dWc1, *dWc2;
    cudaGetSymbolAddress(&p, g_Hh);  dH0 = (__half*)p; dH1 = dH0 + (size_t)NNODES * F2;
    cudaGetSymbolAddress(&p, g_Wc1); dWc1 = (float*)p;
    cudaGetSymbolAddress(&p, g_Wc2); dWc2 = (float*)p;

    const size_t N = NNODES;
    float* lowx = out;
    float* lowy = out + N * 204;
    float* finx = out + 2 * N * 204;
    float* finy = out + 2 * N * 204 + N * 336;
    float* fivx = out + 2 * N * 204 + 2 * N * 336;
    float* mlpx = fivx + N * 128;
    float* fivy = mlpx + N * 132;
    float* mlpy = fivy + N * 128;

    const int MROWBLKS = (NNODES + GBM - 1) / GBM;   // 391
    const int NB8 = (NNODES + 7) / 8;                // 6250

    // 1
    pack_kernel<<<(100352 + 255) / 256, 256>>>(W1, b1, W2, b2, W3, b3, W4, b4, W5, b5);
    // 2
    hist_kernel<<<dim3(1024, 2), 256>>>(a1, a2);
    // 3
    scan1_kernel<<<dim3(SCAN_NB, 2), SCAN_BLK>>>();
    // 4
    fill_kernel<<<dim3(1024, 2), 256>>>(a1, v1, a2, v2);
    // 5: H1 = X @ [W1|W2|W3]  (fp16 out)
    gemm_k<true, false><<<dim3(4, MROWBLKS, 2), 256>>>(x, y, dWc1, dH0, dH1,
                                                       NNODES, 128, F1, nullptr);
    // 6: fused spmm + sigmoid + concat  (ncu capture slot)
    spmm1_kernel<<<dim3(NB8, 2), 256>>>(lowx, lowy);
    // 7: G2 = low @ [W4|W5]  (fp16 out)
    gemm_k<true, false><<<dim3(5, MROWBLKS, 2), 256>>>(lowx, lowy, dWc2, dH0, dH1,
                                                       NNODES, F1, F2, nullptr);
    // 8: spmm -> h_fou (scratch) + h_fiv (output)
    spmm2_kernel<<<dim3(NB8, 2), 256>>>(fivx, fivy);
    // 9: h_mlp = leaky_relu(h_fiv @ Wm + bm)  (fp32 out)
    gemm_k<false, true><<<dim3(3, MROWBLKS, 2), 256>>>(fivx, fivy, Wm, mlpx, mlpy,
                                                       NNODES, 128, 132, bm);
    // 10
    final_kernel<<<dim3(NB8, 2), 256>>>(lowx, lowy, mlpx, mlpy, finx, finy);
}

// round 5
// speedup vs baseline: 2.6474x; 1.4553x over previous
#include <cuda_runtime.h>
#include <cuda_fp16.h>

#define NNODES 50000
#define NEDGES 800000
#define FIN0   128
#define F1     204      // 64+68+72
#define F2     260      // 132+128
#define S4_1   51       // F1/4
#define S4_2   65       // F2/4
#define SCAN_BLK 1024
#define SCAN_NB  49

// ---------------- device scratch ----------------
__device__ __half g_Hh[2][(size_t)NNODES * F2];   // fp16 GEMM outputs (gather operand)
__device__ float  g_fou[2][(size_t)NNODES * 132];
__device__ __half g_Wc1T[F1 * FIN0];              // transposed fp16 weights [n][k]
__device__ __half g_Wc2T[F2 * F1];
__device__ __half g_WmT[132 * 128];
__device__ float  g_bc1[F1];
__device__ float  g_bc2[F2];
__device__ int    g_rowptr[2][NNODES + 2];
__device__ int    g_cnt[2][NNODES];
__device__ int    g_boff[2][64];
__device__ uint2  g_edge[2][NEDGES];              // {col, valbits}

// ---------------- pack weights (fp16, transposed) + zero counters ----------------
__global__ void pack_kernel(const float* __restrict__ W1, const float* __restrict__ b1,
                            const float* __restrict__ W2, const float* __restrict__ b2,
                            const float* __restrict__ W3, const float* __restrict__ b3,
                            const float* __restrict__ W4, const float* __restrict__ b4,
                            const float* __restrict__ W5, const float* __restrict__ b5,
                            const float* __restrict__ Wm) {
    int i = blockIdx.x * blockDim.x + threadIdx.x;
    if (i < F1 * FIN0) {                 // Wc1T[n][k]
        int n = i / FIN0, k = i % FIN0;
        float v = (n < 64) ? W1[k * 64 + n]
                : (n < 132) ? W2[k * 68 + (n - 64)]
                            : W3[k * 72 + (n - 132)];
        g_Wc1T[i] = __float2half(v);
    }
    if (i < F2 * F1) {                   // Wc2T[n][k]
        int n = i / F1, k = i % F1;
        float v = (n < 132) ? W4[k * 132 + n] : W5[k * 128 + (n - 132)];
        g_Wc2T[i] = __float2half(v);
    }
    if (i < 132 * 128) {                 // WmT[n][k]
        int n = i / 128, k = i % 128;
        g_WmT[i] = __float2half(Wm[k * 132 + n]);
    }
    if (i < F1) g_bc1[i] = (i < 64) ? b1[i] : (i < 132) ? b2[i - 64] : b3[i - 132];
    if (i < F2) g_bc2[i] = (i < 132) ? b4[i] : b5[i - 132];
    if (i < NNODES) { g_cnt[0][i] = 0; g_cnt[1][i] = 0; }
    if (i < 64)     { g_boff[0][i] = 0; g_boff[1][i] = 0; }
}

// ---------------- CSR build (int32 idx: row=idx[e], col=idx[E+e]) ----------------
__global__ void hist_kernel(const int* __restrict__ i1, const int* __restrict__ i2) {
    const int br = blockIdx.y;
    const int* idx = br ? i2 : i1;
    int* cnt = g_cnt[br];
    int stride = gridDim.x * blockDim.x;
    for (int e = blockIdx.x * blockDim.x + threadIdx.x; e < NEDGES; e += stride)
        atomicAdd(&cnt[idx[e]], 1);
}

__global__ void __launch_bounds__(SCAN_BLK) scan1_kernel() {
    __shared__ int warp_sums[32];
    __shared__ int sTot;
    const int br = blockIdx.y, b = blockIdx.x, t = threadIdx.x;
    const int i = b * SCAN_BLK + t;
    const int lane = t & 31, wid = t >> 5;
    int v = (i < NNODES) ? g_cnt[br][i] : 0;
    int s = v;
#pragma unroll
    for (int o = 1; o < 32; o <<= 1) {
        int u = __shfl_up_sync(0xFFFFFFFFu, s, o);
        if (lane >= o) s += u;
    }
    if (lane == 31) warp_sums[wid] = s;
    __syncthreads();
    if (wid == 0) {
        int ws = warp_sums[lane];
#pragma unroll
        for (int o = 1; o < 32; o <<= 1) {
            int u = __shfl_up_sync(0xFFFFFFFFu, ws, o);
            if (lane >= o) ws += u;
        }
        warp_sums[lane] = ws;
    }
    __syncthreads();
    int excl = s - v + (wid > 0 ? warp_sums[wid - 1] : 0);
    if (i <= NNODES) g_rowptr[br][i] = excl;
    if (t == SCAN_BLK - 1) sTot = excl + v;
    __syncthreads();
    int total = sTot;
    if (t > b && t < SCAN_NB) atomicAdd(&g_boff[br][t], total);
}

__global__ void fill_kernel(const int* __restrict__ i1, const float* __restrict__ v1,
                            const int* __restrict__ i2, const float* __restrict__ v2) {
    const int br = blockIdx.y;
    const int*   idx = br ? i2 : i1;
    const float* val = br ? v2 : v1;
    int* cnt = g_cnt[br];
    const int* rp = g_rowptr[br];
    const int* bo = g_boff[br];
    uint2* edge = g_edge[br];
    int stride = gridDim.x * blockDim.x;
    for (int e = blockIdx.x * blockDim.x + threadIdx.x; e < NEDGES; e += stride) {
        int r = idx[e];
        int slot = atomicSub(&cnt[r], 1) - 1;
        int pos = rp[r] + bo[r >> 10] + slot;
        edge[pos] = make_uint2((unsigned)idx[NEDGES + e], __float_as_uint(val[e]));
    }
}

// ---------------- fp16 mma.m16n8k16 GEMM: C = act(A @ B + bias) ----------------
// A: [M,K] fp32 row-major; BT: [Nc][K] fp16 (pre-transposed); branch via blockIdx.z
#define GBM 128
#define GBN 64
#define GBK 32

__device__ __forceinline__ unsigned pack_h2(float a, float b) {
    __half2 h = __floats2half2_rn(a, b);
    return *(unsigned*)&h;
}

template<bool OUTH, bool ACT, bool FUSE>
__global__ void __launch_bounds__(256) gemm_k(
    const float* __restrict__ A0, const float* __restrict__ A1,
    const __half* __restrict__ BT,
    void* __restrict__ C0v, void* __restrict__ C1v,
    float* __restrict__ fin0, float* __restrict__ fin1,
    int M, int K, int Nc, const float* __restrict__ bias)
{
    const int z = blockIdx.z;
    const float* A = z ? A1 : A0;
    void* Cv = z ? C1v : C0v;
    __shared__ unsigned As2[GBM][17];   // half2: [row][k/2]
    __shared__ unsigned Bs2[GBN][17];   // half2: [n][k/2]
    const int tid  = threadIdx.x;
    const int row0 = blockIdx.y * GBM;
    const int col0 = blockIdx.x * GBN;
    const int lane = tid & 31;
    const int wid  = tid >> 5;
    const int wm   = (wid & 3) * 32;
    const int wn   = (wid >> 2) * 32;
    const int grp  = lane >> 2;
    const int tig  = lane & 3;
    const unsigned* BT2 = (const unsigned*)BT;
    const int Kh = K >> 1;

    float c[2][4][4];
#pragma unroll
    for (int mi = 0; mi < 2; mi++)
#pragma unroll
        for (int ni = 0; ni < 4; ni++)
#pragma unroll
            for (int e = 0; e < 4; e++) c[mi][ni][e] = 0.f;

    const bool fullM = (row0 + GBM <= M);

    for (int k0 = 0; k0 < K; k0 += GBK) {
        const bool fullK = (k0 + GBK <= K);
        // ---- A tile 128x32 -> half2 ----
        if (fullK && fullM) {
#pragma unroll
            for (int p = 0; p < 4; p++) {
                int linear = tid + p * 256;
                int r = linear >> 3, q = linear & 7;
                const float4 v = *(const float4*)&A[(size_t)(row0 + r) * K + k0 + q * 4];
                As2[r][2 * q]     = pack_h2(v.x, v.y);
                As2[r][2 * q + 1] = pack_h2(v.z, v.w);
            }
        } else {
#pragma unroll
            for (int l = 0; l < 8; l++) {
                int linear = tid + l * 256;
                int r = linear >> 4, k2 = linear & 15;
                int gr = row0 + r, gk = k0 + 2 * k2;
                float f0 = (gr < M && gk < K)     ? A[(size_t)gr * K + gk]     : 0.f;
                float f1 = (gr < M && gk + 1 < K) ? A[(size_t)gr * K + gk + 1] : 0.f;
                As2[r][k2] = pack_h2(f0, f1);
            }
        }
        // ---- B tile 64x32 from pre-transposed fp16 (coalesced) ----
#pragma unroll
        for (int p = 0; p < 4; p++) {
            int linear = tid + p * 256;
            int n = linear >> 4, k2 = linear & 15;
            int gc = col0 + n, gk = k0 + 2 * k2;
            Bs2[n][k2] = (gc < Nc && gk < K) ? BT2[(size_t)gc * Kh + (k0 >> 1) + k2] : 0u;
        }
        __syncthreads();
#pragma unroll
        for (int ks = 0; ks < 2; ks++) {
            const int kb = ks * 8;
            unsigned a[2][4], b[4][2];
#pragma unroll
            for (int mi = 0; mi < 2; mi++) {
                int r = wm + mi * 16 + grp;
                a[mi][0] = As2[r][kb + tig];
                a[mi][1] = As2[r + 8][kb + tig];
                a[mi][2] = As2[r][kb + tig + 4];
                a[mi][3] = As2[r + 8][kb + tig + 4];
            }
#pragma unroll
            for (int ni = 0; ni < 4; ni++) {
                int cn = wn + ni * 8 + grp;
                b[ni][0] = Bs2[cn][kb + tig];
                b[ni][1] = Bs2[cn][kb + tig + 4];
            }
#pragma unroll
            for (int mi = 0; mi < 2; mi++)
#pragma unroll
                for (int ni = 0; ni < 4; ni++)
                    asm volatile(
                        "mma.sync.aligned.m16n8k16.row.col.f32.f16.f16.f32 "
                        "{%0,%1,%2,%3}, {%4,%5,%6,%7}, {%8,%9}, {%0,%1,%2,%3};"
                        : "+f"(c[mi][ni][0]), "+f"(c[mi][ni][1]),
                          "+f"(c[mi][ni][2]), "+f"(c[mi][ni][3])
                        : "r"(a[mi][0]), "r"(a[mi][1]), "r"(a[mi][2]), "r"(a[mi][3]),
                          "r"(b[ni][0]), "r"(b[ni][1]));
        }
        __syncthreads();
    }
    // ---- epilogue (pairwise, cn even) ----
    const float* fou = FUSE ? g_fou[z] : nullptr;
    float* fin = FUSE ? (z ? fin1 : fin0) : nullptr;
#pragma unroll
    for (int mi = 0; mi < 2; mi++)
#pragma unroll
        for (int ni = 0; ni < 4; ni++)
#pragma unroll
            for (int h = 0; h < 2; h++) {
                int r  = row0 + wm + mi * 16 + grp + h * 8;
                int cn = col0 + wn + ni * 8 + tig * 2;
                if (r < M && cn < Nc) {
                    float v0 = c[mi][ni][h * 2 + 0];
                    float v1 = c[mi][ni][h * 2 + 1];
                    if (bias) { v0 += bias[cn]; v1 += bias[cn + 1]; }
                    if (ACT) {
                        v0 = (v0 > 0.f) ? v0 : 0.01f * v0;
                        v1 = (v1 > 0.f) ? v1 : 0.01f * v1;
                    }
                    if (OUTH) {
                        __half2* C = (__half2*)Cv;
                        C[((size_t)r * Nc + cn) >> 1] = __floats2half2_rn(v0, v1);
                    } else {
                        float2* C = (float2*)Cv;
                        C[((size_t)r * Nc + cn) >> 1] = make_float2(v0, v1);
                    }
                    if (FUSE) {   // fin[204+cn] = (mlp + fou)/2
                        float f0v = fou[(size_t)r * 132 + cn];
                        float f1v = fou[(size_t)r * 132 + cn + 1];
                        float2* fp = (float2*)&fin[(size_t)r * 336 + 204 + cn];
                        *fp = make_float2(0.5f * (v0 + f0v), 0.5f * (v1 + f1v));
                    }
                }
            }
}

// ---------------- helpers ----------------
__device__ __forceinline__ float4 sig4(float4 z) {
    float4 r;
    r.x = 1.f / (1.f + __expf(-z.x));
    r.y = 1.f / (1.f + __expf(-z.y));
    r.z = 1.f / (1.f + __expf(-z.z));
    r.w = 1.f / (1.f + __expf(-z.w));
    return r;
}
__device__ __forceinline__ void fma4h(float4& a, float v, uint2 h) {
    float2 lo = __half22float2(*(const __half2*)&h.x);
    float2 hi = __half22float2(*(const __half2*)&h.y);
    a.x += v * lo.x; a.y += v * lo.y; a.z += v * hi.x; a.w += v * hi.y;
}
__device__ __forceinline__ float sum4(float4 a) { return a.x + a.y + a.z + a.w; }

// ---------------- SpMM1 (warp/node): sigmoid+concat; writes low AND fin low-part ----------------
__global__ void __launch_bounds__(256) spmm1_kernel(float* __restrict__ low_x,
                                                    float* __restrict__ low_y,
                                                    float* __restrict__ fin_x,
                                                    float* __restrict__ fin_y) {
    const int lane = threadIdx.x & 31;
    const int i = blockIdx.x * 8 + (threadIdx.x >> 5);
    if (i >= NNODES) return;
    const int br = blockIdx.y;
    const int* rp = g_rowptr[br];
    const int* bo = g_boff[br];
    const uint2* edge = g_edge[br];
    const uint2* H2 = (const uint2*)g_Hh[br];
    float* low = br ? low_y : low_x;
    float* fin = br ? fin_y : fin_x;

    const int s0 = rp[i] + bo[i >> 10];
    const int s1 = rp[i + 1] + bo[(i + 1) >> 10];
    float4 a0 = {0, 0, 0, 0}, a1 = {0, 0, 0, 0};

    for (int e0 = s0; e0 < s1; e0 += 32) {
        int e = e0 + lane;
        uint2 ev = (e < s1) ? edge[e] : make_uint2(0, 0);
        int n = min(32, s1 - e0);
#pragma unroll 4
        for (int j = 0; j < n; j++) {
            int cc  = __shfl_sync(0xFFFFFFFFu, (int)ev.x, j);
            float v = __uint_as_float(__shfl_sync(0xFFFFFFFFu, ev.y, j));
            const uint2* row = H2 + (size_t)cc * S4_1;
            fma4h(a0, v, row[lane]);
            if (lane < S4_1 - 32) fma4h(a1, v, row[32 + lane]);
        }
    }
    const float4* b4 = (const float4*)g_bc1;
    float4 v0 = sig4(make_float4(a0.x + b4[lane].x, a0.y + b4[lane].y,
                                 a0.z + b4[lane].z, a0.w + b4[lane].w));
    float4 v1 = {0, 0, 0, 0};
    if (lane < S4_1 - 32) {
        float4 bb = b4[32 + lane];
        v1 = sig4(make_float4(a1.x + bb.x, a1.y + bb.y, a1.z + bb.z, a1.w + bb.w));
    }
    // mean over h_sec (features 64..131 -> q 16..32)
    float part = 0.f;
    if (lane >= 16) part = sum4(v0);
    if (lane == 0)  part += sum4(v1);
#pragma unroll
    for (int o = 16; o > 0; o >>= 1) part += __shfl_xor_sync(0xFFFFFFFFu, part, o);
    const float mean = part * (1.f / 68.f);

    // lr values
    float4 w0 = v0;
    float4 w1 = (lane == 0) ? v1
              : make_float4(mean * v1.x, mean * v1.y, mean * v1.z, mean * v1.w);
    // mean over full lr (204)
    float tot = sum4(w0);
    if (lane < S4_1 - 32) tot += sum4(w1);
#pragma unroll
    for (int o = 16; o > 0; o >>= 1) tot += __shfl_xor_sync(0xFFFFFFFFu, tot, o);
    const float s = 1.f + tot * (1.f / 204.f);

    float4* lw = (float4*)(low + (size_t)i * F1);
    float4* fn = (float4*)(fin + (size_t)i * 336);
    lw[lane] = w0;
    fn[lane] = make_float4(s * w0.x, s * w0.y, s * w0.z, s * w0.w);
    if (lane < S4_1 - 32) {
        lw[32 + lane] = w1;
        fn[32 + lane] = make_float4(s * w1.x, s * w1.y, s * w1.z, s * w1.w);
    }
}

// ---------------- SpMM2 (warp/node): +bias -> h_fou (scratch), h_fiv (out) ----------------
__global__ void __launch_bounds__(256) spmm2_kernel(float* __restrict__ fiv_x,
                                                    float* __restrict__ fiv_y) {
    const int lane = threadIdx.x & 31;
    const int i = blockIdx.x * 8 + (threadIdx.x >> 5);
    if (i >= NNODES) return;
    const int br = blockIdx.y;
    const int* rp = g_rowptr[br];
    const int* bo = g_boff[br];
    const uint2* edge = g_edge[br];
    const uint2* H2 = (const uint2*)g_Hh[br];
    float* fiv = br ? fiv_y : fiv_x;
    float4* fou4 = (float4*)g_fou[br];

    const int s0 = rp[i] + bo[i >> 10];
    const int s1 = rp[i + 1] + bo[(i + 1) >> 10];
    float4 a0 = {0, 0, 0, 0}, a1 = {0, 0, 0, 0}, a2 = {0, 0, 0, 0};

    for (int e0 = s0; e0 < s1; e0 += 32) {
        int e = e0 + lane;
        uint2 ev = (e < s1) ? edge[e] : make_uint2(0, 0);
        int n = min(32, s1 - e0);
#pragma unroll 4
        for (int j = 0; j < n; j++) {
            int cc  = __shfl_sync(0xFFFFFFFFu, (int)ev.x, j);
            float v = __uint_as_float(__shfl_sync(0xFFFFFFFFu, ev.y, j));
            const uint2* row = H2 + (size_t)cc * S4_2;
            fma4h(a0, v, row[lane]);
            fma4h(a1, v, row[32 + lane]);
            if (lane == 0) fma4h(a2, v, row[64]);
        }
    }
    const float4* b4 = (const float4*)g_bc2;
    float4 bb0 = b4[lane], bb1 = b4[32 + lane];
    float4 z0 = make_float4(a0.x + bb0.x, a0.y + bb0.y, a0.z + bb0.z, a0.w + bb0.w);
    float4 z1 = make_float4(a1.x + bb1.x, a1.y + bb1.y, a1.z + bb1.z, a1.w + bb1.w);
    float4* fv4 = (float4*)(fiv + (size_t)i * 128);
    fou4[(size_t)i * 33 + lane] = z0;
    if (lane == 0) {
        fou4[(size_t)i * 33 + 32] = z1;
        float4 bb2 = b4[64];
        fv4[31] = make_float4(a2.x + bb2.x, a2.y + bb2.y, a2.z + bb2.z, a2.w + bb2.w);
    } else {
        fv4[lane - 1] = z1;
    }
}

// ---------------- launch ----------------
extern "C" void kernel_launch(void* const* d_in, const int* in_sizes, int n_in,
                              void* d_out, int out_size) {
    const float* x  = (const float*)d_in[0];
    const int*   a1 = (const int*)d_in[1];
    const float* v1 = (const float*)d_in[2];
    const float* y  = (const float*)d_in[3];
    const int*   a2 = (const int*)d_in[4];
    const float* v2 = (const float*)d_in[5];
    const float* W1 = (const float*)d_in[6];
    const float* b1 = (const float*)d_in[7];
    const float* W2 = (const float*)d_in[8];
    const float* b2 = (const float*)d_in[9];
    const float* W3 = (const float*)d_in[10];
    const float* b3 = (const float*)d_in[11];
    const float* W4 = (const float*)d_in[12];
    const float* b4 = (const float*)d_in[13];
    const float* W5 = (const float*)d_in[14];
    const float* b5 = (const float*)d_in[15];
    const float* Wm = (const float*)d_in[16];
    const float* bm = (const float*)d_in[17];
    float* out = (float*)d_out;

    void* p;
    __half *dH0, *dH1, *dW1T, *dW2T, *dWmT;
    cudaGetSymbolAddress(&p, g_Hh);   dH0 = (__half*)p; dH1 = dH0 + (size_t)NNODES * F2;
    cudaGetSymbolAddress(&p, g_Wc1T); dW1T = (__half*)p;
    cudaGetSymbolAddress(&p, g_Wc2T); dW2T = (__half*)p;
    cudaGetSymbolAddress(&p, g_WmT);  dWmT = (__half*)p;

    const size_t N = NNODES;
    float* lowx = out;
    float* lowy = out + N * 204;
    float* finx = out + 2 * N * 204;
    float* finy = out + 2 * N * 204 + N * 336;
    float* fivx = out + 2 * N * 204 + 2 * N * 336;
    float* mlpx = fivx + N * 128;
    float* fivy = mlpx + N * 132;
    float* mlpy = fivy + N * 128;

    const int MROWBLKS = (NNODES + GBM - 1) / GBM;   // 391
    const int NB8 = (NNODES + 7) / 8;                // 6250

    pack_kernel<<<(F2 * F1 + 255) / 256, 256>>>(W1, b1, W2, b2, W3, b3, W4, b4, W5, b5, Wm);
    hist_kernel<<<dim3(1024, 2), 256>>>(a1, a2);
    scan1_kernel<<<dim3(SCAN_NB, 2), SCAN_BLK>>>();
    fill_kernel<<<dim3(1024, 2), 256>>>(a1, v1, a2, v2);
    // H1 = X @ [W1|W2|W3]  (fp16 out)
    gemm_k<true, false, false><<<dim3(4, MROWBLKS, 2), 256>>>(
        x, y, dW1T, dH0, dH1, nullptr, nullptr, NNODES, 128, F1, nullptr);
    // fused spmm + sigmoid + concat + fin-low
    spmm1_kernel<<<dim3(NB8, 2), 256>>>(lowx, lowy, finx, finy);
    // G2 = low @ [W4|W5]  (fp16 out)
    gemm_k<true, false, false><<<dim3(5, MROWBLKS, 2), 256>>>(
        lowx, lowy, dW2T, dH0, dH1, nullptr, nullptr, NNODES, F1, F2, nullptr);
    // spmm -> h_fou (scratch) + h_fiv (output)
    spmm2_kernel<<<dim3(NB8, 2), 256>>>(fivx, fivy);
    // h_mlp = leaky_relu(fiv @ Wm + bm); fused f3 = (mlp+fou)/2 into fin
    gemm_k<false, true, true><<<dim3(3, MROWBLKS, 2), 256>>>(
        fivx, fivy, dWmT, mlpx, mlpy, finx, finy, NNODES, 128, 132, bm);
}

// round 6
// speedup vs baseline: 2.8875x; 1.0907x over previous
#include <cuda_runtime.h>
#include <cuda_fp16.h>

#define NNODES 50000
#define NEDGES 800000
#define FIN0   128
#define F1     204      // 64+68+72
#define F2     260      // 132+128
#define S4_1   51       // F1/4
#define S4_2   65       // F2/4
#define SCAN_NB  49

// ---------------- device scratch ----------------
__device__ __half g_Hh[2][(size_t)NNODES * F2];    // GEMM1/GEMM2 fp16 outputs (gather operand)
__device__ __half g_lowh[2][(size_t)NNODES * F1];  // fp16 copy of low_result (GEMM2 A)
__device__ __half g_fivh[2][(size_t)NNODES * 128]; // fp16 copy of h_fiv (GEMM3 A)
__device__ float  g_fou[2][(size_t)NNODES * 132];
__device__ __half g_Wc1T[F1 * FIN0];               // transposed fp16 weights [n][k]
__device__ __half g_Wc2T[F2 * F1];
__device__ __half g_WmT[132 * 128];
__device__ float  g_bc1[F1];
__device__ float  g_bc2[F2];
__device__ int    g_rowptr[2][NNODES + 2];
__device__ int    g_cnt[2][NNODES];   // ALWAYS zero between runs: fill's atomicSub restores it
__device__ int    g_boff[2][64];
__device__ uint2  g_edge[2][NEDGES];  // {col, valbits}

// ---------------- fused pack (y==0, x<208) + hist (rest) ----------------
// Safe: hist touches only g_cnt (atomics); pack never writes g_cnt (fill restores it to 0).
#define PACK_BLKS 208
__global__ void __launch_bounds__(256) pack_hist_kernel(
    const float* __restrict__ W1, const float* __restrict__ b1,
    const float* __restrict__ W2, const float* __restrict__ b2,
    const float* __restrict__ W3, const float* __restrict__ b3,
    const float* __restrict__ W4, const float* __restrict__ b4,
    const float* __restrict__ W5, const float* __restrict__ b5,
    const float* __restrict__ Wm,
    const int* __restrict__ i1, const int* __restrict__ i2)
{
    const int t = threadIdx.x;
    if (blockIdx.y == 0 && blockIdx.x < PACK_BLKS) {
        int i = blockIdx.x * 256 + t;
        if (i < F1 * FIN0) {                 // Wc1T[n][k]
            int n = i / FIN0, k = i % FIN0;
            float v = (n < 64) ? W1[k * 64 + n]
                    : (n < 132) ? W2[k * 68 + (n - 64)]
                                : W3[k * 72 + (n - 132)];
            g_Wc1T[i] = __float2half(v);
        }
        if (i < F2 * F1) {                   // Wc2T[n][k]
            int n = i / F1, k = i % F1;
            float v = (n < 132) ? W4[k * 132 + n] : W5[k * 128 + (n - 132)];
            g_Wc2T[i] = __float2half(v);
        }
        if (i < 132 * 128) {                 // WmT[n][k]
            int n = i / 128, k = i % 128;
            g_WmT[i] = __float2half(Wm[k * 132 + n]);
        }
        if (i < F1) g_bc1[i] = (i < 64) ? b1[i] : (i < 132) ? b2[i - 64] : b3[i - 132];
        if (i < F2) g_bc2[i] = (i < 132) ? b4[i] : b5[i - 132];
        if (i < 64) { g_boff[0][i] = 0; g_boff[1][i] = 0; }
    } else {
        const int br = blockIdx.y;
        const int* idx = br ? i2 : i1;
        int* cnt = g_cnt[br];
        int nb = gridDim.x - (br == 0 ? PACK_BLKS : 0);
        int bx = blockIdx.x - (br == 0 ? PACK_BLKS : 0);
        int stride = nb * 256;
        for (int e = bx * 256 + t; e < NEDGES; e += stride)
            atomicAdd(&cnt[idx[e]], 1);
    }
}

// ---------------- scan ----------------
__global__ void __launch_bounds__(1024) scan1_kernel() {
    __shared__ int warp_sums[32];
    __shared__ int sTot;
    const int br = blockIdx.y, b = blockIdx.x, t = threadIdx.x;
    const int i = b * 1024 + t;
    const int lane = t & 31, wid = t >> 5;
    int v = (i < NNODES) ? g_cnt[br][i] : 0;
    int s = v;
#pragma unroll
    for (int o = 1; o < 32; o <<= 1) {
        int u = __shfl_up_sync(0xFFFFFFFFu, s, o);
        if (lane >= o) s += u;
    }
    if (lane == 31) warp_sums[wid] = s;
    __syncthreads();
    if (wid == 0) {
        int ws = warp_sums[lane];
#pragma unroll
        for (int o = 1; o < 32; o <<= 1) {
            int u = __shfl_up_sync(0xFFFFFFFFu, ws, o);
            if (lane >= o) ws += u;
        }
        warp_sums[lane] = ws;
    }
    __syncthreads();
    int excl = s - v + (wid > 0 ? warp_sums[wid - 1] : 0);
    if (i <= NNODES) g_rowptr[br][i] = excl;
    if (t == 1023) sTot = excl + v;
    __syncthreads();
    int total = sTot;
    if (t > b && t < SCAN_NB) atomicAdd(&g_boff[br][t], total);
}

// ---------------- GEMM body: C = act(A @ BT^T + bias) ----------------
#define GBM 128
#define GBN 64
#define GBK 32

__device__ __forceinline__ unsigned pack_h2(float a, float b) {
    __half2 h = __floats2half2_rn(a, b);
    return *(unsigned*)&h;
}

template<bool OUTH, bool ACT, bool FUSE, bool AH>
__device__ __forceinline__ void gemm_body(
    const void* __restrict__ Av, const __half* __restrict__ BT,
    void* __restrict__ Cv, float* __restrict__ fin, const float* __restrict__ fou,
    int M, int K, int Nc, const float* __restrict__ bias, int row0, int col0)
{
    __shared__ unsigned As2[GBM][17];   // half2: [row][k/2]
    __shared__ unsigned Bs2[GBN][17];   // half2: [n][k/2]
    const int tid  = threadIdx.x;
    const int lane = tid & 31;
    const int wid  = tid >> 5;
    const int wm   = (wid & 3) * 32;
    const int wn   = (wid >> 2) * 32;
    const int grp  = lane >> 2;
    const int tig  = lane & 3;
    const unsigned* BT2 = (const unsigned*)BT;
    const int Kh = K >> 1;

    float c[2][4][4];
#pragma unroll
    for (int mi = 0; mi < 2; mi++)
#pragma unroll
        for (int ni = 0; ni < 4; ni++)
#pragma unroll
            for (int e = 0; e < 4; e++) c[mi][ni][e] = 0.f;

    const bool fullM = (row0 + GBM <= M);

    for (int k0 = 0; k0 < K; k0 += GBK) {
        const bool fullK = (k0 + GBK <= K);
        if (AH) {
            const unsigned* A2 = (const unsigned*)Av;
#pragma unroll
            for (int l = 0; l < 8; l++) {
                int linear = tid + l * 256;
                int r = linear >> 4, k2 = linear & 15;
                int gr = row0 + r, gk2 = (k0 >> 1) + k2;
                As2[r][k2] = (gr < M && gk2 < Kh) ? A2[(size_t)gr * Kh + gk2] : 0u;
            }
        } else {
            const float* A = (const float*)Av;
            if (fullK && fullM) {
#pragma unroll
                for (int p = 0; p < 4; p++) {
                    int linear = tid + p * 256;
                    int r = linear >> 3, q = linear & 7;
                    const float4 v = *(const float4*)&A[(size_t)(row0 + r) * K + k0 + q * 4];
                    As2[r][2 * q]     = pack_h2(v.x, v.y);
                    As2[r][2 * q + 1] = pack_h2(v.z, v.w);
                }
            } else {
#pragma unroll
                for (int l = 0; l < 8; l++) {
                    int linear = tid + l * 256;
                    int r = linear >> 4, k2 = linear & 15;
                    int gr = row0 + r, gk = k0 + 2 * k2;
                    float f0 = (gr < M && gk < K)     ? A[(size_t)gr * K + gk]     : 0.f;
                    float f1 = (gr < M && gk + 1 < K) ? A[(size_t)gr * K + gk + 1] : 0.f;
                    As2[r][k2] = pack_h2(f0, f1);
                }
            }
        }
#pragma unroll
        for (int p = 0; p < 4; p++) {
            int linear = tid + p * 256;
            int n = linear >> 4, k2 = linear & 15;
            int gc = col0 + n, gk2 = (k0 >> 1) + k2;
            Bs2[n][k2] = (gc < Nc && gk2 < Kh) ? BT2[(size_t)gc * Kh + gk2] : 0u;
        }
        __syncthreads();
#pragma unroll
        for (int ks = 0; ks < 2; ks++) {
            const int kb = ks * 8;
            unsigned a[2][4], b[4][2];
#pragma unroll
            for (int mi = 0; mi < 2; mi++) {
                int r = wm + mi * 16 + grp;
                a[mi][0] = As2[r][kb + tig];
                a[mi][1] = As2[r + 8][kb + tig];
                a[mi][2] = As2[r][kb + tig + 4];
                a[mi][3] = As2[r + 8][kb + tig + 4];
            }
#pragma unroll
            for (int ni = 0; ni < 4; ni++) {
                int cn = wn + ni * 8 + grp;
                b[ni][0] = Bs2[cn][kb + tig];
                b[ni][1] = Bs2[cn][kb + tig + 4];
            }
#pragma unroll
            for (int mi = 0; mi < 2; mi++)
#pragma unroll
                for (int ni = 0; ni < 4; ni++)
                    asm volatile(
                        "mma.sync.aligned.m16n8k16.row.col.f32.f16.f16.f32 "
                        "{%0,%1,%2,%3}, {%4,%5,%6,%7}, {%8,%9}, {%0,%1,%2,%3};"
                        : "+f"(c[mi][ni][0]), "+f"(c[mi][ni][1]),
                          "+f"(c[mi][ni][2]), "+f"(c[mi][ni][3])
                        : "r"(a[mi][0]), "r"(a[mi][1]), "r"(a[mi][2]), "r"(a[mi][3]),
                          "r"(b[ni][0]), "r"(b[ni][1]));
        }
        __syncthreads();
    }
#pragma unroll
    for (int mi = 0; mi < 2; mi++)
#pragma unroll
        for (int ni = 0; ni < 4; ni++)
#pragma unroll
            for (int h = 0; h < 2; h++) {
                int r  = row0 + wm + mi * 16 + grp + h * 8;
                int cn = col0 + wn + ni * 8 + tig * 2;
                if (r < M && cn < Nc) {
                    float v0 = c[mi][ni][h * 2 + 0];
                    float v1 = c[mi][ni][h * 2 + 1];
                    if (bias) { v0 += bias[cn]; v1 += bias[cn + 1]; }
                    if (ACT) {
                        v0 = (v0 > 0.f) ? v0 : 0.01f * v0;
                        v1 = (v1 > 0.f) ? v1 : 0.01f * v1;
                    }
                    if (OUTH) {
                        unsigned* C = (unsigned*)Cv;
                        C[((size_t)r * Nc + cn) >> 1] = pack_h2(v0, v1);
                    } else {
                        float2* C = (float2*)Cv;
                        C[((size_t)r * Nc + cn) >> 1] = make_float2(v0, v1);
                    }
                    if (FUSE) {   // fin[204+cn] = (mlp + fou)/2
                        float f0v = fou[(size_t)r * 132 + cn];
                        float f1v = fou[(size_t)r * 132 + cn + 1];
                        float2* fp = (float2*)&fin[(size_t)r * 336 + 204 + cn];
                        *fp = make_float2(0.5f * (v0 + f0v), 0.5f * (v1 + f1v));
                    }
                }
            }
}

// ---------------- fused fill (y<256) + GEMM1 (y>=256) ----------------
#define FILL_Y 256
__global__ void __launch_bounds__(256) fill_gemm1_kernel(
    const int* __restrict__ i1, const float* __restrict__ v1,
    const int* __restrict__ i2, const float* __restrict__ v2,
    const float* __restrict__ x, const float* __restrict__ y)
{
    const int z = blockIdx.z;
    if (blockIdx.y < FILL_Y) {
        const int*   idx = z ? i2 : i1;
        const float* val = z ? v2 : v1;
        int* cnt = g_cnt[z];
        const int* rp = g_rowptr[z];
        const int* bo = g_boff[z];
        uint2* edge = g_edge[z];
        const int stride = FILL_Y * 4 * 256;
        for (int e = (blockIdx.y * 4 + blockIdx.x) * 256 + threadIdx.x;
             e < NEDGES; e += stride) {
            int r = idx[e];
            int slot = atomicSub(&cnt[r], 1) - 1;    // restores cnt to 0 when done
            int pos = rp[r] + bo[r >> 10] + slot;
            edge[pos] = make_uint2((unsigned)idx[NEDGES + e], __float_as_uint(val[e]));
        }
    } else {
        gemm_body<true, false, false, false>(
            z ? y : x, g_Wc1T, g_Hh[z], nullptr, nullptr,
            NNODES, FIN0, F1, nullptr,
            (blockIdx.y - FILL_Y) * GBM, blockIdx.x * GBN);
    }
}

__global__ void __launch_bounds__(256) gemm2_kernel() {
    const int z = blockIdx.z;
    gemm_body<true, false, false, true>(
        g_lowh[z], g_Wc2T, g_Hh[z], nullptr, nullptr,
        NNODES, F1, F2, nullptr, blockIdx.y * GBM, blockIdx.x * GBN);
}

__global__ void __launch_bounds__(256) gemm3_kernel(float* mlp_x, float* mlp_y,
                                                    float* fin_x, float* fin_y,
                                                    const float* __restrict__ bm) {
    const int z = blockIdx.z;
    gemm_body<false, true, true, true>(
        g_fivh[z], g_WmT, z ? mlp_y : mlp_x, z ? fin_y : fin_x, g_fou[z],
        NNODES, 128, 132, bm, blockIdx.y * GBM, blockIdx.x * GBN);
}

// ---------------- helpers ----------------
__device__ __forceinline__ float4 sig4(float4 z) {
    float4 r;
    r.x = 1.f / (1.f + __expf(-z.x));
    r.y = 1.f / (1.f + __expf(-z.y));
    r.z = 1.f / (1.f + __expf(-z.z));
    r.w = 1.f / (1.f + __expf(-z.w));
    return r;
}
__device__ __forceinline__ void fma4h(float4& a, float v, uint2 h) {
    float2 lo = __half22float2(*(const __half2*)&h.x);
    float2 hi = __half22float2(*(const __half2*)&h.y);
    a.x += v * lo.x; a.y += v * lo.y; a.z += v * hi.x; a.w += v * hi.y;
}
__device__ __forceinline__ float sum4(float4 a) { return a.x + a.y + a.z + a.w; }
__device__ __forceinline__ uint2 h2x2(float4 v) {
    return make_uint2(pack_h2(v.x, v.y), pack_h2(v.z, v.w));
}

// ---------------- SpMM1 (warp/node): sigmoid+concat -> low, fin-low, lowh ----------------
__global__ void __launch_bounds__(256) spmm1_kernel(float* __restrict__ low_x,
                                                    float* __restrict__ low_y,
                                                    float* __restrict__ fin_x,
                                                    float* __restrict__ fin_y) {
    const int lane = threadIdx.x & 31;
    const int i = blockIdx.x * 8 + (threadIdx.x >> 5);
    if (i >= NNODES) return;
    const int br = blockIdx.y;
    const int* rp = g_rowptr[br];
    const int* bo = g_boff[br];
    const uint2* edge = g_edge[br];
    const uint2* H2 = (const uint2*)g_Hh[br];
    float* low = br ? low_y : low_x;
    float* fin = br ? fin_y : fin_x;

    const int s0 = rp[i] + bo[i >> 10];
    const int s1 = rp[i + 1] + bo[(i + 1) >> 10];
    float4 a0 = {0, 0, 0, 0}, a1 = {0, 0, 0, 0};

    for (int e0 = s0; e0 < s1; e0 += 32) {
        int e = e0 + lane;
        uint2 ev = (e < s1) ? edge[e] : make_uint2(0, 0);
        int n = min(32, s1 - e0);
#pragma unroll 4
        for (int j = 0; j < n; j++) {
            int cc  = __shfl_sync(0xFFFFFFFFu, (int)ev.x, j);
            float v = __uint_as_float(__shfl_sync(0xFFFFFFFFu, ev.y, j));
            const uint2* row = H2 + (size_t)cc * S4_1;
            fma4h(a0, v, row[lane]);
            if (lane < S4_1 - 32) fma4h(a1, v, row[32 + lane]);
        }
    }
    const float4* b4 = (const float4*)g_bc1;
    float4 v0 = sig4(make_float4(a0.x + b4[lane].x, a0.y + b4[lane].y,
                                 a0.z + b4[lane].z, a0.w + b4[lane].w));
    float4 v1 = {0, 0, 0, 0};
    if (lane < S4_1 - 32) {
        float4 bb = b4[32 + lane];
        v1 = sig4(make_float4(a1.x + bb.x, a1.y + bb.y, a1.z + bb.z, a1.w + bb.w));
    }
    // mean over h_sec (features 64..131)
    float part = 0.f;
    if (lane >= 16) part = sum4(v0);
    if (lane == 0)  part += sum4(v1);
#pragma unroll
    for (int o = 16; o > 0; o >>= 1) part += __shfl_xor_sync(0xFFFFFFFFu, part, o);
    const float mean = part * (1.f / 68.f);

    float4 w0 = v0;
    float4 w1 = (lane == 0) ? v1
              : make_float4(mean * v1.x, mean * v1.y, mean * v1.z, mean * v1.w);
    float tot = sum4(w0);
    if (lane < S4_1 - 32) tot += sum4(w1);
#pragma unroll
    for (int o = 16; o > 0; o >>= 1) tot += __shfl_xor_sync(0xFFFFFFFFu, tot, o);
    const float s = 1.f + tot * (1.f / 204.f);

    float4* lw = (float4*)(low + (size_t)i * F1);
    float4* fn = (float4*)(fin + (size_t)i * 336);
    uint2*  lh = (uint2*)(g_lowh[br] + (size_t)i * F1);
    lw[lane] = w0;
    fn[lane] = make_float4(s * w0.x, s * w0.y, s * w0.z, s * w0.w);
    lh[lane] = h2x2(w0);
    if (lane < S4_1 - 32) {
        lw[32 + lane] = w1;
        fn[32 + lane] = make_float4(s * w1.x, s * w1.y, s * w1.z, s * w1.w);
        lh[32 + lane] = h2x2(w1);
    }
}

// ---------------- SpMM2 (warp/node): +bias -> h_fou (scratch), h_fiv (out), fivh ----------------
__global__ void __launch_bounds__(256) spmm2_kernel(float* __restrict__ fiv_x,
                                                    float* __restrict__ fiv_y) {
    const int lane = threadIdx.x & 31;
    const int i = blockIdx.x * 8 + (threadIdx.x >> 5);
    if (i >= NNODES) return;
    const int br = blockIdx.y;
    const int* rp = g_rowptr[br];
    const int* bo = g_boff[br];
    const uint2* edge = g_edge[br];
    const uint2* H2 = (const uint2*)g_Hh[br];
    float* fiv = br ? fiv_y : fiv_x;
    float4* fou4 = (float4*)g_fou[br];
    uint2*  fh = (uint2*)(g_fivh[br] + (size_t)i * 128);

    const int s0 = rp[i] + bo[i >> 10];
    const int s1 = rp[i + 1] + bo[(i + 1) >> 10];
    float4 a0 = {0, 0, 0, 0}, a1 = {0, 0, 0, 0}, a2 = {0, 0, 0, 0};

    for (int e0 = s0; e0 < s1; e0 += 32) {
        int e = e0 + lane;
        uint2 ev = (e < s1) ? edge[e] : make_uint2(0, 0);
        int n = min(32, s1 - e0);
#pragma unroll 4
        for (int j = 0; j < n; j++) {
            int cc  = __shfl_sync(0xFFFFFFFFu, (int)ev.x, j);
            float v = __uint_as_float(__shfl_sync(0xFFFFFFFFu, ev.y, j));
            const uint2* row = H2 + (size_t)cc * S4_2;
            fma4h(a0, v, row[lane]);
            fma4h(a1, v, row[32 + lane]);
            if (lane == 0) fma4h(a2, v, row[64]);
        }
    }
    const float4* b4 = (const float4*)g_bc2;
    float4 bb0 = b4[lane], bb1 = b4[32 + lane];
    float4 z0 = make_float4(a0.x + bb0.x, a0.y + bb0.y, a0.z + bb0.z, a0.w + bb0.w);
    float4 z1 = make_float4(a1.x + bb1.x, a1.y + bb1.y, a1.z + bb1.z, a1.w + bb1.w);
    float4* fv4 = (float4*)(fiv + (size_t)i * 128);
    fou4[(size_t)i * 33 + lane] = z0;
    if (lane == 0) {
        fou4[(size_t)i * 33 + 32] = z1;
        float4 bb2 = b4[64];
        float4 z2 = make_float4(a2.x + bb2.x, a2.y + bb2.y, a2.z + bb2.z, a2.w + bb2.w);
        fv4[31] = z2;
        fh[31] = h2x2(z2);
    } else {
        fv4[lane - 1] = z1;
        fh[lane - 1] = h2x2(z1);
    }
}

// ---------------- launch ----------------
extern "C" void kernel_launch(void* const* d_in, const int* in_sizes, int n_in,
                              void* d_out, int out_size) {
    const float* x  = (const float*)d_in[0];
    const int*   a1 = (const int*)d_in[1];
    const float* v1 = (const float*)d_in[2];
    const float* y  = (const float*)d_in[3];
    const int*   a2 = (const int*)d_in[4];
    const float* v2 = (const float*)d_in[5];
    const float* W1 = (const float*)d_in[6];
    const float* b1 = (const float*)d_in[7];
    const float* W2 = (const float*)d_in[8];
    const float* b2 = (const float*)d_in[9];
    const float* W3 = (const float*)d_in[10];
    const float* b3 = (const float*)d_in[11];
    const float* W4 = (const float*)d_in[12];
    const float* b4 = (const float*)d_in[13];
    const float* W5 = (const float*)d_in[14];
    const float* b5 = (const float*)d_in[15];
    const float* Wm = (const float*)d_in[16];
    const float* bm = (const float*)d_in[17];
    float* out = (float*)d_out;

    const size_t N = NNODES;
    float* lowx = out;
    float* lowy = out + N * 204;
    float* finx = out + 2 * N * 204;
    float* finy = out + 2 * N * 204 + N * 336;
    float* fivx = out + 2 * N * 204 + 2 * N * 336;
    float* mlpx = fivx + N * 128;
    float* fivy = mlpx + N * 132;
    float* mlpy = fivy + N * 128;

    const int MROWBLKS = (NNODES + GBM - 1) / GBM;   // 391
    const int NB8 = (NNODES + 7) / 8;                // 6250

    // 1: pack weights + histogram (fused, independent block ranges)
    pack_hist_kernel<<<dim3(PACK_BLKS + 1024, 2), 256>>>(
        W1, b1, W2, b2, W3, b3, W4, b4, W5, b5, Wm, a1, a2);
    // 2: rowptr scan
    scan1_kernel<<<dim3(SCAN_NB, 2), 1024>>>();
    // 3: fill CSR + GEMM1 (fused; independent)
    fill_gemm1_kernel<<<dim3(4, FILL_Y + MROWBLKS, 2), 256>>>(a1, v1, a2, v2, x, y);
    // 4: fused spmm + sigmoid + concat + fin-low + fp16 copy
    spmm1_kernel<<<dim3(NB8, 2), 256>>>(lowx, lowy, finx, finy);
    // 5: G2 = low @ [W4|W5] (fp16 A, fp16 out)
    gemm2_kernel<<<dim3(5, MROWBLKS, 2), 256>>>();
    // 6: spmm -> h_fou (scratch) + h_fiv (output) + fp16 copy
    spmm2_kernel<<<dim3(NB8, 2), 256>>>(fivx, fivy);
    // 7: h_mlp = leaky_relu(fiv @ Wm + bm); fused f3 = (mlp+fou)/2
    gemm3_kernel<<<dim3(3, MROWBLKS, 2), 256>>>(mlpx, mlpy, finx, finy, bm);
}

// round 7
// speedup vs baseline: 2.9702x; 1.0286x over previous
#include <cuda_runtime.h>
#include <cuda_fp16.h>

#define NNODES 50000
#define NEDGES 800000
#define FIN0   128
#define F1     204      // 64+68+72
#define F2     260      // 132+128
#define LD1    208      // padded halves stride for H1 / lowh (16B-aligned rows)
#define LD2    264      // padded halves stride for H2
#define SCAN_NB  49

// ---------------- device scratch ----------------
__device__ __align__(16) __half g_Hh[2][(size_t)NNODES * LD2];    // GEMM1 (stride LD1) then GEMM2 (stride LD2)
__device__ __align__(16) __half g_lowh[2][(size_t)NNODES * LD1];  // fp16 low_result (GEMM2 A)
__device__ __align__(16) __half g_fivh[2][(size_t)NNODES * 128];  // fp16 h_fiv (GEMM3 A)
__device__ __align__(16) float  g_fou[2][(size_t)NNODES * 132];
__device__ __align__(16) __half g_Wc1T[F1 * FIN0];                // transposed fp16 weights [n][k]
__device__ __align__(16) __half g_Wc2T[F2 * F1];
__device__ __align__(16) __half g_WmT[132 * 128];
__device__ __align__(16) float  g_bc1[256];   // padded, pad stays zero
__device__ __align__(16) float  g_bc2[F2];    // 260 = 65 float4
__device__ int    g_rowptr[2][NNODES + 2];
__device__ int    g_cnt[2][NNODES];   // always zero between runs: fill's atomicSub restores it
__device__ int    g_boff[2][64];
__device__ __align__(8) uint2  g_edge[2][NEDGES];  // {col, valbits}

// ---------------- fused pack (y==0, x<208) + hist (rest) ----------------
#define PACK_BLKS 208
__global__ void __launch_bounds__(256) pack_hist_kernel(
    const float* __restrict__ W1, const float* __restrict__ b1,
    const float* __restrict__ W2, const float* __restrict__ b2,
    const float* __restrict__ W3, const float* __restrict__ b3,
    const float* __restrict__ W4, const float* __restrict__ b4,
    const float* __restrict__ W5, const float* __restrict__ b5,
    const float* __restrict__ Wm,
    const int* __restrict__ i1, const int* __restrict__ i2)
{
    const int t = threadIdx.x;
    if (blockIdx.y == 0 && blockIdx.x < PACK_BLKS) {
        int i = blockIdx.x * 256 + t;
        if (i < F1 * FIN0) {                 // Wc1T[n][k]
            int n = i / FIN0, k = i % FIN0;
            float v = (n < 64) ? W1[k * 64 + n]
                    : (n < 132) ? W2[k * 68 + (n - 64)]
                                : W3[k * 72 + (n - 132)];
            g_Wc1T[i] = __float2half(v);
        }
        if (i < F2 * F1) {                   // Wc2T[n][k]
            int n = i / F1, k = i % F1;
            float v = (n < 132) ? W4[k * 132 + n] : W5[k * 128 + (n - 132)];
            g_Wc2T[i] = __float2half(v);
        }
        if (i < 132 * 128) {                 // WmT[n][k]
            int n = i / 128, k = i % 128;
            g_WmT[i] = __float2half(Wm[k * 132 + n]);
        }
        if (i < F1) g_bc1[i] = (i < 64) ? b1[i] : (i < 132) ? b2[i - 64] : b3[i - 132];
        if (i < F2) g_bc2[i] = (i < 132) ? b4[i] : b5[i - 132];
        if (i < 64) { g_boff[0][i] = 0; g_boff[1][i] = 0; }
    } else {
        const int br = blockIdx.y;
        const int* idx = br ? i2 : i1;
        int* cnt = g_cnt[br];
        int nb = gridDim.x - (br == 0 ? PACK_BLKS : 0);
        int bx = blockIdx.x - (br == 0 ? PACK_BLKS : 0);
        int stride = nb * 256;
        for (int e = bx * 256 + t; e < NEDGES; e += stride)
            atomicAdd(&cnt[idx[e]], 1);
    }
}

// ---------------- scan ----------------
__global__ void __launch_bounds__(1024) scan1_kernel() {
    __shared__ int warp_sums[32];
    __shared__ int sTot;
    const int br = blockIdx.y, b = blockIdx.x, t = threadIdx.x;
    const int i = b * 1024 + t;
    const int lane = t & 31, wid = t >> 5;
    int v = (i < NNODES) ? g_cnt[br][i] : 0;
    int s = v;
#pragma unroll
    for (int o = 1; o < 32; o <<= 1) {
        int u = __shfl_up_sync(0xFFFFFFFFu, s, o);
        if (lane >= o) s += u;
    }
    if (lane == 31) warp_sums[wid] = s;
    __syncthreads();
    if (wid == 0) {
        int ws = warp_sums[lane];
#pragma unroll
        for (int o = 1; o < 32; o <<= 1) {
            int u = __shfl_up_sync(0xFFFFFFFFu, ws, o);
            if (lane >= o) ws += u;
        }
        warp_sums[lane] = ws;
    }
    __syncthreads();
    int excl = s - v + (wid > 0 ? warp_sums[wid - 1] : 0);
    if (i <= NNODES) g_rowptr[br][i] = excl;
    if (t == 1023) sTot = excl + v;
    __syncthreads();
    int total = sTot;
    if (t > b && t < SCAN_NB) atomicAdd(&g_boff[br][t], total);
}

// ---------------- GEMM body ----------------
#define GBM 128
#define GBN 64
#define GBK 32

__device__ __forceinline__ unsigned pack_h2(float a, float b) {
    __half2 h = __floats2half2_rn(a, b);
    return *(unsigned*)&h;
}

template<bool OUTH, bool ACT, bool FUSE, bool AH>
__device__ __forceinline__ void gemm_body(
    const void* __restrict__ Av, const __half* __restrict__ BT,
    void* __restrict__ Cv, float* __restrict__ fin, const float* __restrict__ fou,
    int M, int K, int Nc, const float* __restrict__ bias,
    int lda2, int ldc, int row0, int col0)
{
    __shared__ unsigned As2[GBM][17];   // half2: [row][k/2]
    __shared__ unsigned Bs2[GBN][17];   // half2: [n][k/2]
    const int tid  = threadIdx.x;
    const int lane = tid & 31;
    const int wid  = tid >> 5;
    const int wm   = (wid & 3) * 32;
    const int wn   = (wid >> 2) * 32;
    const int grp  = lane >> 2;
    const int tig  = lane & 3;
    const unsigned* BT2 = (const unsigned*)BT;
    const int Kh = K >> 1;

    float c[2][4][4];
#pragma unroll
    for (int mi = 0; mi < 2; mi++)
#pragma unroll
        for (int ni = 0; ni < 4; ni++)
#pragma unroll
            for (int e = 0; e < 4; e++) c[mi][ni][e] = 0.f;

    const bool fullM = (row0 + GBM <= M);

    for (int k0 = 0; k0 < K; k0 += GBK) {
        const bool fullK = (k0 + GBK <= K);
        if (AH) {
            const unsigned* A2 = (const unsigned*)Av;
#pragma unroll
            for (int l = 0; l < 8; l++) {
                int linear = tid + l * 256;
                int r = linear >> 4, k2 = linear & 15;
                int gr = row0 + r, gk2 = (k0 >> 1) + k2;
                As2[r][k2] = (gr < M && gk2 < Kh) ? A2[(size_t)gr * lda2 + gk2] : 0u;
            }
        } else {
            const float* A = (const float*)Av;
            if (fullK && fullM) {
#pragma unroll
                for (int p = 0; p < 4; p++) {
                    int linear = tid + p * 256;
                    int r = linear >> 3, q = linear & 7;
                    const float4 v = *(const float4*)&A[(size_t)(row0 + r) * K + k0 + q * 4];
                    As2[r][2 * q]     = pack_h2(v.x, v.y);
                    As2[r][2 * q + 1] = pack_h2(v.z, v.w);
                }
            } else {
#pragma unroll
                for (int l = 0; l < 8; l++) {
                    int linear = tid + l * 256;
                    int r = linear >> 4, k2 = linear & 15;
                    int gr = row0 + r, gk = k0 + 2 * k2;
                    float f0 = (gr < M && gk < K)     ? A[(size_t)gr * K + gk]     : 0.f;
                    float f1 = (gr < M && gk + 1 < K) ? A[(size_t)gr * K + gk + 1] : 0.f;
                    As2[r][k2] = pack_h2(f0, f1);
                }
            }
        }
#pragma unroll
        for (int p = 0; p < 4; p++) {
            int linear = tid + p * 256;
            int n = linear >> 4, k2 = linear & 15;
            int gc = col0 + n, gk2 = (k0 >> 1) + k2;
            Bs2[n][k2] = (gc < Nc && gk2 < Kh) ? BT2[(size_t)gc * Kh + gk2] : 0u;
        }
        __syncthreads();
#pragma unroll
        for (int ks = 0; ks < 2; ks++) {
            const int kb = ks * 8;
            unsigned a[2][4], b[4][2];
#pragma unroll
            for (int mi = 0; mi < 2; mi++) {
                int r = wm + mi * 16 + grp;
                a[mi][0] = As2[r][kb + tig];
                a[mi][1] = As2[r + 8][kb + tig];
                a[mi][2] = As2[r][kb + tig + 4];
                a[mi][3] = As2[r + 8][kb + tig + 4];
            }
#pragma unroll
            for (int ni = 0; ni < 4; ni++) {
                int cn = wn + ni * 8 + grp;
                b[ni][0] = Bs2[cn][kb + tig];
                b[ni][1] = Bs2[cn][kb + tig + 4];
            }
#pragma unroll
            for (int mi = 0; mi < 2; mi++)
#pragma unroll
                for (int ni = 0; ni < 4; ni++)
                    asm volatile(
                        "mma.sync.aligned.m16n8k16.row.col.f32.f16.f16.f32 "
                        "{%0,%1,%2,%3}, {%4,%5,%6,%7}, {%8,%9}, {%0,%1,%2,%3};"
                        : "+f"(c[mi][ni][0]), "+f"(c[mi][ni][1]),
                          "+f"(c[mi][ni][2]), "+f"(c[mi][ni][3])
                        : "r"(a[mi][0]), "r"(a[mi][1]), "r"(a[mi][2]), "r"(a[mi][3]),
                          "r"(b[ni][0]), "r"(b[ni][1]));
        }
        __syncthreads();
    }
#pragma unroll
    for (int mi = 0; mi < 2; mi++)
#pragma unroll
        for (int ni = 0; ni < 4; ni++)
#pragma unroll
            for (int h = 0; h < 2; h++) {
                int r  = row0 + wm + mi * 16 + grp + h * 8;
                int cn = col0 + wn + ni * 8 + tig * 2;
                if (r < M && cn < Nc) {
                    float v0 = c[mi][ni][h * 2 + 0];
                    float v1 = c[mi][ni][h * 2 + 1];
                    if (bias) { v0 += bias[cn]; v1 += bias[cn + 1]; }
                    if (ACT) {
                        v0 = (v0 > 0.f) ? v0 : 0.01f * v0;
                        v1 = (v1 > 0.f) ? v1 : 0.01f * v1;
                    }
                    if (OUTH) {
                        unsigned* C = (unsigned*)Cv;
                        C[((size_t)r * ldc + cn) >> 1] = pack_h2(v0, v1);
                    } else {
                        float2* C = (float2*)Cv;
                        C[((size_t)r * ldc + cn) >> 1] = make_float2(v0, v1);
                    }
                    if (FUSE) {
                        float f0v = fou[(size_t)r * 132 + cn];
                        float f1v = fou[(size_t)r * 132 + cn + 1];
                        float2* fp = (float2*)&fin[(size_t)r * 336 + 204 + cn];
                        *fp = make_float2(0.5f * (v0 + f0v), 0.5f * (v1 + f1v));
                    }
                }
            }
}

// ---------------- fused fill (y<256) + GEMM1 (y>=256) ----------------
#define FILL_Y 256
__global__ void __launch_bounds__(256) fill_gemm1_kernel(
    const int* __restrict__ i1, const float* __restrict__ v1,
    const int* __restrict__ i2, const float* __restrict__ v2,
    const float* __restrict__ x, const float* __restrict__ y)
{
    const int z = blockIdx.z;
    if (blockIdx.y < FILL_Y) {
        const int*   idx = z ? i2 : i1;
        const float* val = z ? v2 : v1;
        int* cnt = g_cnt[z];
        const int* rp = g_rowptr[z];
        const int* bo = g_boff[z];
        uint2* edge = g_edge[z];
        const int stride = FILL_Y * 4 * 256;
        for (int e = (blockIdx.y * 4 + blockIdx.x) * 256 + threadIdx.x;
             e < NEDGES; e += stride) {
            int r = idx[e];
            int slot = atomicSub(&cnt[r], 1) - 1;
            int pos = rp[r] + bo[r >> 10] + slot;
            edge[pos] = make_uint2((unsigned)idx[NEDGES + e], __float_as_uint(val[e]));
        }
    } else {
        gemm_body<true, false, false, false>(
            z ? y : x, g_Wc1T, g_Hh[z], nullptr, nullptr,
            NNODES, FIN0, F1, nullptr, 0, LD1,
            (blockIdx.y - FILL_Y) * GBM, blockIdx.x * GBN);
    }
}

__global__ void __launch_bounds__(256) gemm2_kernel() {
    const int z = blockIdx.z;
    gemm_body<true, false, false, true>(
        g_lowh[z], g_Wc2T, g_Hh[z], nullptr, nullptr,
        NNODES, F1, F2, nullptr, LD1 / 2, LD2, blockIdx.y * GBM, blockIdx.x * GBN);
}

__global__ void __launch_bounds__(256) gemm3_kernel(float* mlp_x, float* mlp_y,
                                                    float* fin_x, float* fin_y,
                                                    const float* __restrict__ bm) {
    const int z = blockIdx.z;
    gemm_body<false, true, true, true>(
        g_fivh[z], g_WmT, z ? mlp_y : mlp_x, z ? fin_y : fin_x, g_fou[z],
        NNODES, 128, 132, bm, 64, 132, blockIdx.y * GBM, blockIdx.x * GBN);
}

// ---------------- helpers ----------------
__device__ __forceinline__ float4 sig4(float4 z) {
    float4 r;
    r.x = 1.f / (1.f + __expf(-z.x));
    r.y = 1.f / (1.f + __expf(-z.y));
    r.z = 1.f / (1.f + __expf(-z.z));
    r.w = 1.f / (1.f + __expf(-z.w));
    return r;
}
__device__ __forceinline__ float4 add4(float4 a, float4 b) {
    return make_float4(a.x + b.x, a.y + b.y, a.z + b.z, a.w + b.w);
}
__device__ __forceinline__ float4 mul4(float4 a, float s) {
    return make_float4(s * a.x, s * a.y, s * a.z, s * a.w);
}
__device__ __forceinline__ void fma4h(float4& a, float v, uint2 h) {
    float2 lo = __half22float2(*(const __half2*)&h.x);
    float2 hi = __half22float2(*(const __half2*)&h.y);
    a.x += v * lo.x; a.y += v * lo.y; a.z += v * hi.x; a.w += v * hi.y;
}
__device__ __forceinline__ float sum4(float4 a) { return a.x + a.y + a.z + a.w; }
__device__ __forceinline__ uint2 h2x2(float4 v) {
    return make_uint2(pack_h2(v.x, v.y), pack_h2(v.z, v.w));
}

// ---------------- SpMM1 (warp/node, uniform edge load, uint4 gather) ----------------
__global__ void __launch_bounds__(256) spmm1_kernel(float* __restrict__ low_x,
                                                    float* __restrict__ low_y,
                                                    float* __restrict__ fin_x,
                                                    float* __restrict__ fin_y) {
    const int lane = threadIdx.x & 31;
    const int i = blockIdx.x * 8 + (threadIdx.x >> 5);
    if (i >= NNODES) return;
    const int br = blockIdx.y;
    const int s0 = g_rowptr[br][i]     + g_boff[br][i >> 10];
    const int s1 = g_rowptr[br][i + 1] + g_boff[br][(i + 1) >> 10];
    const uint2* __restrict__ edge = g_edge[br];
    const __half* __restrict__ Hb = g_Hh[br];
    float* low = br ? low_y : low_x;
    float* fin = br ? fin_y : fin_x;

    float4 a0 = {0, 0, 0, 0}, a1 = {0, 0, 0, 0};
#pragma unroll 4
    for (int e = s0; e < s1; e++) {
        const uint2 ev = edge[e];                       // uniform: L1 broadcast
        const float v = __uint_as_float(ev.y);
        const uint4* row = (const uint4*)(Hb + (size_t)ev.x * LD1);
        if (lane < 26) {
            uint4 h = row[lane];                        // 8 features
            fma4h(a0, v, make_uint2(h.x, h.y));
            fma4h(a1, v, make_uint2(h.z, h.w));
        }
    }
    const float4* b4 = (const float4*)g_bc1;
    float4 v0 = sig4(add4(a0, b4[2 * lane]));
    float4 v1 = sig4(add4(a1, b4[2 * lane + 1]));
    // mean over h_sec (features 64..131 = lanes 8..15 full, lane 16 first 4)
    float part = 0.f;
    if (lane >= 8 && lane < 16) part = sum4(v0) + sum4(v1);
    if (lane == 16) part = sum4(v0);
#pragma unroll
    for (int o = 16; o > 0; o >>= 1) part += __shfl_xor_sync(0xFFFFFFFFu, part, o);
    const float mean = part * (1.f / 68.f);
    // h_thi scaling (features 132..203)
    float4 w0 = v0, w1 = v1;
    if (lane == 16) w1 = mul4(v1, mean);
    if (lane >= 17) { w0 = mul4(v0, mean); w1 = mul4(v1, mean); }
    // mean over full lr (204 = lanes 0..24 full, lane 25 first 4)
    float tot = 0.f;
    if (lane < 25) tot = sum4(w0) + sum4(w1);
    if (lane == 25) tot = sum4(w0);
#pragma unroll
    for (int o = 16; o > 0; o >>= 1) tot += __shfl_xor_sync(0xFFFFFFFFu, tot, o);
    const float s = 1.f + tot * (1.f / 204.f);

    float4* lw = (float4*)(low + (size_t)i * F1);
    float4* fn = (float4*)(fin + (size_t)i * 336);
    uint4*  lh = (uint4*)(g_lowh[br] + (size_t)i * LD1);
    if (lane < 26) {
        lh[lane] = make_uint4(pack_h2(w0.x, w0.y), pack_h2(w0.z, w0.w),
                              pack_h2(w1.x, w1.y), pack_h2(w1.z, w1.w));
        lw[2 * lane] = w0;
        fn[2 * lane] = mul4(w0, s);
        if (lane < 25) {
            lw[2 * lane + 1] = w1;
            fn[2 * lane + 1] = mul4(w1, s);
        }
    }
}

// ---------------- SpMM2 (warp/node): +bias -> fou (scratch), fiv (out), fivh ----------------
__global__ void __launch_bounds__(256) spmm2_kernel(float* __restrict__ fiv_x,
                                                    float* __restrict__ fiv_y) {
    const int lane = threadIdx.x & 31;
    const int i = blockIdx.x * 8 + (threadIdx.x >> 5);
    if (i >= NNODES) return;
    const int br = blockIdx.y;
    const int s0 = g_rowptr[br][i]     + g_boff[br][i >> 10];
    const int s1 = g_rowptr[br][i + 1] + g_boff[br][(i + 1) >> 10];
    const uint2* __restrict__ edge = g_edge[br];
    const __half* __restrict__ Hb = g_Hh[br];

    float4 a0 = {0, 0, 0, 0}, a1 = {0, 0, 0, 0}, ax = {0, 0, 0, 0};
#pragma unroll 4
    for (int e = s0; e < s1; e++) {
        const uint2 ev = edge[e];                       // uniform: L1 broadcast
        const float v = __uint_as_float(ev.y);
        const __half* rowp = Hb + (size_t)ev.x * LD2;
        uint4 h = ((const uint4*)rowp)[lane];           // features 8*lane..8*lane+7
        fma4h(a0, v, make_uint2(h.x, h.y));
        fma4h(a1, v, make_uint2(h.z, h.w));
        if (lane == 0) {
            uint2 hx = ((const uint2*)rowp)[64];        // features 256..259
            fma4h(ax, v, hx);
        }
    }
    const float4* b4 = (const float4*)g_bc2;            // 65 float4
    float4 z0 = add4(a0, b4[2 * lane]);
    float4 z1 = add4(a1, b4[2 * lane + 1]);
    float* fiv = br ? fiv_y : fiv_x;
    float4* fou4 = (float4*)g_fou[br] + (size_t)i * 33;
    float4* fiv4 = (float4*)(fiv + (size_t)i * 128);
    uint2*  fh   = (uint2*)(g_fivh[br] + (size_t)i * 128);
    if (lane < 16) {
        fou4[2 * lane] = z0;
        fou4[2 * lane + 1] = z1;
    } else if (lane == 16) {
        fou4[32] = z0;                                  // f128..131
        fiv4[0] = z1;  fh[0] = h2x2(z1);                // f132..135
    } else {
        int idx = 2 * (lane - 17) + 1;
        fiv4[idx] = z0;      fh[idx] = h2x2(z0);
        fiv4[idx + 1] = z1;  fh[idx + 1] = h2x2(z1);
    }
    if (lane == 0) {
        float4 zx = add4(ax, b4[64]);                   // f256..259
        fiv4[31] = zx;  fh[31] = h2x2(zx);
    }
}

// ---------------- launch ----------------
extern "C" void kernel_launch(void* const* d_in, const int* in_sizes, int n_in,
                              void* d_out, int out_size) {
    const float* x  = (const float*)d_in[0];
    const int*   a1 = (const int*)d_in[1];
    const float* v1 = (const float*)d_in[2];
    const float* y  = (const float*)d_in[3];
    const int*   a2 = (const int*)d_in[4];
    const float* v2 = (const float*)d_in[5];
    const float* W1 = (const float*)d_in[6];
    const float* b1 = (const float*)d_in[7];
    const float* W2 = (const float*)d_in[8];
    const float* b2 = (const float*)d_in[9];
    const float* W3 = (const float*)d_in[10];
    const float* b3 = (const float*)d_in[11];
    const float* W4 = (const float*)d_in[12];
    const float* b4 = (const float*)d_in[13];
    const float* W5 = (const float*)d_in[14];
    const float* b5 = (const float*)d_in[15];
    const float* Wm = (const float*)d_in[16];
    const float* bm = (const float*)d_in[17];
    float* out = (float*)d_out;

    const size_t N = NNODES;
    float* lowx = out;
    float* lowy = out + N * 204;
    float* finx = out + 2 * N * 204;
    float* finy = out + 2 * N * 204 + N * 336;
    float* fivx = out + 2 * N * 204 + 2 * N * 336;
    float* mlpx = fivx + N * 128;
    float* fivy = mlpx + N * 132;
    float* mlpy = fivy + N * 128;

    const int MROWBLKS = (NNODES + GBM - 1) / GBM;   // 391
    const int NB8 = (NNODES + 7) / 8;                // 6250

    pack_hist_kernel<<<dim3(PACK_BLKS + 1024, 2), 256>>>(
        W1, b1, W2, b2, W3, b3, W4, b4, W5, b5, Wm, a1, a2);
    scan1_kernel<<<dim3(SCAN_NB, 2), 1024>>>();
    fill_gemm1_kernel<<<dim3(4, FILL_Y + MROWBLKS, 2), 256>>>(a1, v1, a2, v2, x, y);
    spmm1_kernel<<<dim3(NB8, 2), 256>>>(lowx, lowy, finx, finy);
    gemm2_kernel<<<dim3(5, MROWBLKS, 2), 256>>>();
    spmm2_kernel<<<dim3(NB8, 2), 256>>>(fivx, fivy);
    gemm3_kernel<<<dim3(3, MROWBLKS, 2), 256>>>(mlpx, mlpy, finx, finy, bm);
}